// round 1
// baseline (speedup 1.0000x reference)
#include <cuda_runtime.h>
#include <math.h>

#define B_ 32
#define N_ 256
#define D_ 512
#define H_ 8
#define DH_ 64
#define F_ 2048
#define L_ 8
#define LC_ 2
#define NTOK_ 257

// ---------------- scratch (device globals; no allocation allowed) ----------------
static __device__ float g_h [B_*N_*D_];
static __device__ float g_hn[B_*N_*D_];
static __device__ float g_q [B_*N_*D_];
static __device__ float g_k [B_*N_*D_];
static __device__ float g_v [B_*N_*D_];
static __device__ float g_ao[B_*N_*D_];
static __device__ float g_s [B_*H_*N_*N_];   // 16.8M floats
static __device__ float g_t [B_*N_*F_];      // 16.8M floats
static __device__ float g_cn[B_*NTOK_*D_];
static __device__ float g_kh[B_*NTOK_*D_];
static __device__ float g_vh[B_*NTOK_*D_];
static __device__ float g_qh[B_*D_];
static __device__ float g_co[B_*D_];
static __device__ float g_query[B_*D_];
static __device__ float g_cfn[B_*D_];
static __device__ float g_cff[B_*F_];
static __device__ int   g_mask_mode;

// ---------------- mask dtype detection ----------------
// mask[0,0..127] are guaranteed true (lengths >= N/2). Interpret first word:
//   int32 storage  -> 0x00000001
//   uint8 storage  -> 0x01010101
//   float32 storage-> 0x3F800000
__global__ void detect_mask_kernel(const unsigned int* m) {
    unsigned int w = m[0];
    int mode = 0;                       // int32
    if (w == 0x01010101u) mode = 1;     // uint8 / bool
    else if (w == 0x3F800000u) mode = 2;// float32
    g_mask_mode = mode;
}

__device__ __forceinline__ bool mget(const void* m, int idx) {
    int mode = g_mask_mode;
    if (mode == 1) return ((const unsigned char*)m)[idx] != 0;
    if (mode == 2) return ((const float*)m)[idx] != 0.0f;
    return ((const int*)m)[idx] != 0;
}

// ---------------- tiny utility kernels ----------------
__global__ void copy_kernel(const float* __restrict__ src, float* __restrict__ dst, int n) {
    int i = blockIdx.x * 256 + threadIdx.x;
    if (i < n) dst[i] = src[i];
}

__global__ void bcast_token_kernel(const float* __restrict__ tok) {
    int i = blockIdx.x * 256 + threadIdx.x;   // B_*D_ total
    if (i < B_*D_) g_query[i] = tok[i % D_];
}

// ---------------- LayerNorm (eps = 1e-3, keras default) ----------------
__device__ __forceinline__ void ln_row(const float* __restrict__ x, float* __restrict__ o,
                                       const float* __restrict__ g, const float* __restrict__ bb) {
    int tid = threadIdx.x; // 128 threads
    float s = 0.f, s2 = 0.f;
    #pragma unroll
    for (int i = tid; i < D_; i += 128) { float v = x[i]; s += v; s2 += v * v; }
    __shared__ float sh[8];
    #pragma unroll
    for (int off = 16; off; off >>= 1) {
        s  += __shfl_xor_sync(0xffffffffu, s,  off);
        s2 += __shfl_xor_sync(0xffffffffu, s2, off);
    }
    if ((tid & 31) == 0) { sh[tid >> 5] = s; sh[4 + (tid >> 5)] = s2; }
    __syncthreads();
    s  = sh[0] + sh[1] + sh[2] + sh[3];
    s2 = sh[4] + sh[5] + sh[6] + sh[7];
    float mean = s * (1.f / D_);
    float var  = s2 * (1.f / D_) - mean * mean;
    float r = rsqrtf(var + 1e-3f);
    #pragma unroll
    for (int i = tid; i < D_; i += 128) o[i] = (x[i] - mean) * r * g[i] + bb[i];
}

__global__ void ln_kernel(const float* __restrict__ in, float* __restrict__ out,
                          const float* __restrict__ g, const float* __restrict__ b) {
    long row = blockIdx.x;
    ln_row(in + row * D_, out + row * D_, g, b);
}

// LN over concat([query, h]) rows: row = b*NTOK_ + sidx
__global__ void ln_cat_kernel(const float* __restrict__ query, const float* __restrict__ h,
                              float* __restrict__ out,
                              const float* __restrict__ g, const float* __restrict__ b) {
    int row = blockIdx.x;
    int bb = row / NTOK_, sidx = row % NTOK_;
    const float* x = (sidx == 0) ? (query + (long)bb * D_)
                                 : (h + ((long)(bb * N_) + sidx - 1) * D_);
    ln_row(x, out + (long)row * D_, g, b);
}

// ---------------- generic tiled GEMM with fused epilogue ----------------
// C[m,n] = epi( sum_k A[m,k] * B[k,n] )   (TRANSB: B[n,k])
// batch offset: z1 = z/zdiv, z2 = z%zdiv; ptr += z1*s?1 + z2*s?2
template<int TRANSB>
__global__ void __launch_bounds__(256) gemm_kernel(
    const float* __restrict__ A, const float* __restrict__ Bm, float* __restrict__ C,
    int M, int Nn, int K, int lda, int ldb, int ldc,
    int zdiv, long sA1, long sA2, long sB1, long sB2, long sC1, long sC2,
    const float* __restrict__ bias, const float* __restrict__ res, int ldr,
    long sR1, long sR2, int act)
{
    __shared__ float As[16][65];
    __shared__ float Bs[16][64];
    int z = blockIdx.z;
    long z1 = z / zdiv, z2 = z % zdiv;
    A  += z1 * sA1 + z2 * sA2;
    Bm += z1 * sB1 + z2 * sB2;
    C  += z1 * sC1 + z2 * sC2;
    if (res) res += z1 * sR1 + z2 * sR2;
    const int m0 = blockIdx.y * 64, n0 = blockIdx.x * 64;
    const int tid = threadIdx.x;
    const int tm = tid >> 4, tn = tid & 15;
    const int lr = tid >> 2;            // 0..63
    const int lc = (tid & 3) << 2;      // 0,4,8,12
    const int br = tid >> 4;            // 0..15
    const int bc = (tid & 15) << 2;     // 0..60
    float acc[4][4] = {};
    for (int k0 = 0; k0 < K; k0 += 16) {
        float4 av = make_float4(0.f, 0.f, 0.f, 0.f);
        if (m0 + lr < M) av = *(const float4*)(A + (long)(m0 + lr) * lda + (k0 + lc));
        As[lc + 0][lr] = av.x; As[lc + 1][lr] = av.y;
        As[lc + 2][lr] = av.z; As[lc + 3][lr] = av.w;
        if (TRANSB) {
            float4 bv = make_float4(0.f, 0.f, 0.f, 0.f);
            if (n0 + lr < Nn) bv = *(const float4*)(Bm + (long)(n0 + lr) * ldb + (k0 + lc));
            Bs[lc + 0][lr] = bv.x; Bs[lc + 1][lr] = bv.y;
            Bs[lc + 2][lr] = bv.z; Bs[lc + 3][lr] = bv.w;
        } else {
            float4 bv = *(const float4*)(Bm + (long)(k0 + br) * ldb + (n0 + bc));
            Bs[br][bc + 0] = bv.x; Bs[br][bc + 1] = bv.y;
            Bs[br][bc + 2] = bv.z; Bs[br][bc + 3] = bv.w;
        }
        __syncthreads();
        #pragma unroll
        for (int kk = 0; kk < 16; kk++) {
            float a0 = As[kk][tm], a1 = As[kk][tm + 16],
                  a2 = As[kk][tm + 32], a3 = As[kk][tm + 48];
            float4 b4 = *(const float4*)&Bs[kk][tn << 2];
            acc[0][0] += a0 * b4.x; acc[0][1] += a0 * b4.y; acc[0][2] += a0 * b4.z; acc[0][3] += a0 * b4.w;
            acc[1][0] += a1 * b4.x; acc[1][1] += a1 * b4.y; acc[1][2] += a1 * b4.z; acc[1][3] += a1 * b4.w;
            acc[2][0] += a2 * b4.x; acc[2][1] += a2 * b4.y; acc[2][2] += a2 * b4.z; acc[2][3] += a2 * b4.w;
            acc[3][0] += a3 * b4.x; acc[3][1] += a3 * b4.y; acc[3][2] += a3 * b4.z; acc[3][3] += a3 * b4.w;
        }
        __syncthreads();
    }
    const int n = n0 + (tn << 2);
    float4 bsv = make_float4(0.f, 0.f, 0.f, 0.f);
    if (bias) bsv = *(const float4*)(bias + n);
    #pragma unroll
    for (int i = 0; i < 4; i++) {
        int m = m0 + tm + 16 * i;
        if (m >= M) continue;
        float4 v = make_float4(acc[i][0], acc[i][1], acc[i][2], acc[i][3]);
        if (bias) { v.x += bsv.x; v.y += bsv.y; v.z += bsv.z; v.w += bsv.w; }
        if (act) { // exact gelu: 0.5*x*(1+erf(x/sqrt(2)))
            v.x = 0.5f * v.x * (1.f + erff(v.x * 0.70710678118654752f));
            v.y = 0.5f * v.y * (1.f + erff(v.y * 0.70710678118654752f));
            v.z = 0.5f * v.z * (1.f + erff(v.z * 0.70710678118654752f));
            v.w = 0.5f * v.w * (1.f + erff(v.w * 0.70710678118654752f));
        }
        if (res) {
            float4 r = *(const float4*)(res + (long)m * ldr + n);
            v.x += r.x; v.y += r.y; v.z += r.z; v.w += r.w;
        }
        *(float4*)(C + (long)m * ldc + n) = v;
    }
}

// ---------------- masked softmax with interaction bias ----------------
// row = b*H*N + h*N + qi ; in-place on s[row, 0..N)
__global__ void attn_softmax_kernel(float* __restrict__ s, const float* __restrict__ inter,
                                    const void* __restrict__ mask) {
    long row = blockIdx.x;
    int qi = row % N_;
    int h  = (row / N_) % H_;
    int b  = row / ((long)N_ * H_);
    int k  = threadIdx.x; // 256 threads, one key each
    float* srow = s + row * N_;
    bool qm = mget(mask, b * N_ + qi);
    bool km = mget(mask, b * N_ + k);
    float v = srow[k] * 0.125f
            + inter[((long)(b * N_ + qi) * N_ + k) * H_ + h]
            + ((qm && km) ? 0.f : -1e9f);
    __shared__ float red[9];
    float m = v;
    #pragma unroll
    for (int off = 16; off; off >>= 1) m = fmaxf(m, __shfl_xor_sync(0xffffffffu, m, off));
    if ((k & 31) == 0) red[k >> 5] = m;
    __syncthreads();
    if (k < 32) {
        float t = (k < 8) ? red[k] : -3.0e38f;
        #pragma unroll
        for (int off = 4; off; off >>= 1) t = fmaxf(t, __shfl_xor_sync(0xffffffffu, t, off));
        if (k == 0) red[8] = t;
    }
    __syncthreads();
    m = red[8];
    float e = expf(v - m);
    float ssum = e;
    #pragma unroll
    for (int off = 16; off; off >>= 1) ssum += __shfl_xor_sync(0xffffffffu, ssum, off);
    __syncthreads();
    if ((k & 31) == 0) red[k >> 5] = ssum;
    __syncthreads();
    if (k < 32) {
        float t = (k < 8) ? red[k] : 0.f;
        #pragma unroll
        for (int off = 4; off; off >>= 1) t += __shfl_xor_sync(0xffffffffu, t, off);
        if (k == 0) red[8] = t;
    }
    __syncthreads();
    srow[k] = e / red[8];
}

// ---------------- class attention core (per b,h) ----------------
__global__ void cattn_kernel(const float* __restrict__ qh, const float* __restrict__ kh,
                             const float* __restrict__ vh, float* __restrict__ co,
                             const void* __restrict__ mask) {
    int z = blockIdx.x;
    int b = z / H_, h = z % H_;
    int tid = threadIdx.x; // 128 threads
    __shared__ float a[NTOK_];
    __shared__ float red[4];
    const float* qv = qh + (long)b * D_ + h * DH_;
    float lmax = -3.0e38f;
    for (int sidx = tid; sidx < NTOK_; sidx += 128) {
        const float* kv = kh + ((long)(b * NTOK_ + sidx)) * D_ + h * DH_;
        float sc = 0.f;
        #pragma unroll
        for (int d = 0; d < DH_; d++) sc += qv[d] * kv[d];
        sc = sc * 0.125f + ((sidx == 0 || mget(mask, b * N_ + sidx - 1)) ? 0.f : -1e9f);
        a[sidx] = sc;
        lmax = fmaxf(lmax, sc);
    }
    #pragma unroll
    for (int off = 16; off; off >>= 1) lmax = fmaxf(lmax, __shfl_xor_sync(0xffffffffu, lmax, off));
    if ((tid & 31) == 0) red[tid >> 5] = lmax;
    __syncthreads();
    float m = fmaxf(fmaxf(red[0], red[1]), fmaxf(red[2], red[3]));
    __syncthreads();
    float lsum = 0.f;
    for (int sidx = tid; sidx < NTOK_; sidx += 128) {
        float e = expf(a[sidx] - m);
        a[sidx] = e;
        lsum += e;
    }
    #pragma unroll
    for (int off = 16; off; off >>= 1) lsum += __shfl_xor_sync(0xffffffffu, lsum, off);
    if ((tid & 31) == 0) red[tid >> 5] = lsum;
    __syncthreads();
    float inv = 1.f / (red[0] + red[1] + red[2] + red[3]);
    if (tid < DH_) {
        float o = 0.f;
        for (int sidx = 0; sidx < NTOK_; sidx++)
            o += a[sidx] * vh[((long)(b * NTOK_ + sidx)) * D_ + h * DH_ + tid];
        co[(long)b * D_ + h * DH_ + tid] = o * inv;
    }
}

// ---------------- host-side launch helper ----------------
static void launch_gemm(const float* A, const float* Bm, float* C,
                        int M, int Nn, int K, int lda, int ldb, int ldc,
                        const float* bias, const float* res, int ldr, int act,
                        int nz, int zdiv,
                        long sA1, long sA2, long sB1, long sB2, long sC1, long sC2,
                        long sR1, long sR2, bool transb) {
    dim3 grid(Nn / 64, (M + 63) / 64, nz);
    if (transb)
        gemm_kernel<1><<<grid, 256>>>(A, Bm, C, M, Nn, K, lda, ldb, ldc,
                                      zdiv, sA1, sA2, sB1, sB2, sC1, sC2,
                                      bias, res, ldr, sR1, sR2, act);
    else
        gemm_kernel<0><<<grid, 256>>>(A, Bm, C, M, Nn, K, lda, ldb, ldc,
                                      zdiv, sA1, sA2, sB1, sB2, sC1, sC2,
                                      bias, res, ldr, sR1, sR2, act);
}

static void launch_gemm_simple(const float* A, const float* Bm, float* C,
                               int M, int Nn, int K, int lda, int ldb, int ldc,
                               const float* bias, const float* res, int ldr, int act) {
    launch_gemm(A, Bm, C, M, Nn, K, lda, ldb, ldc, bias, res, ldr, act,
                1, 1, 0, 0, 0, 0, 0, 0, 0, 0, false);
}

extern "C" void kernel_launch(void* const* d_in, const int* in_sizes, int n_in,
                              void* d_out, int out_size) {
    const float* x       = (const float*)d_in[0];
    const float* inter   = (const float*)d_in[1];
    const float* ctok    = (const float*)d_in[2];
    const float* p_ln1_g = (const float*)d_in[3];
    const float* p_ln1_b = (const float*)d_in[4];
    const float* p_wq    = (const float*)d_in[5];
    const float* p_wk    = (const float*)d_in[6];
    const float* p_wv    = (const float*)d_in[7];
    const float* p_wo    = (const float*)d_in[8];
    const float* p_ln2_g = (const float*)d_in[9];
    const float* p_ln2_b = (const float*)d_in[10];
    const float* p_w1    = (const float*)d_in[11];
    const float* p_b1    = (const float*)d_in[12];
    const float* p_w2    = (const float*)d_in[13];
    const float* p_b2    = (const float*)d_in[14];
    const float* c_ln1_g = (const float*)d_in[15];
    const float* c_ln1_b = (const float*)d_in[16];
    const float* c_qk    = (const float*)d_in[17];
    const float* c_qb    = (const float*)d_in[18];
    const float* c_kk    = (const float*)d_in[19];
    const float* c_kb    = (const float*)d_in[20];
    const float* c_vk    = (const float*)d_in[21];
    const float* c_vb    = (const float*)d_in[22];
    const float* c_ok    = (const float*)d_in[23];
    const float* c_ob    = (const float*)d_in[24];
    const float* c_ln2_g = (const float*)d_in[25];
    const float* c_ln2_b = (const float*)d_in[26];
    const float* c_w1    = (const float*)d_in[27];
    const float* c_b1    = (const float*)d_in[28];
    const float* c_w2    = (const float*)d_in[29];
    const float* c_b2    = (const float*)d_in[30];
    const void*  mask    = d_in[31];

    float *h, *hn, *q, *k, *v, *ao, *s, *t, *cn, *kh, *vh, *qh, *co, *query, *cfn, *cff;
    cudaGetSymbolAddress((void**)&h,  g_h);
    cudaGetSymbolAddress((void**)&hn, g_hn);
    cudaGetSymbolAddress((void**)&q,  g_q);
    cudaGetSymbolAddress((void**)&k,  g_k);
    cudaGetSymbolAddress((void**)&v,  g_v);
    cudaGetSymbolAddress((void**)&ao, g_ao);
    cudaGetSymbolAddress((void**)&s,  g_s);
    cudaGetSymbolAddress((void**)&t,  g_t);
    cudaGetSymbolAddress((void**)&cn, g_cn);
    cudaGetSymbolAddress((void**)&kh, g_kh);
    cudaGetSymbolAddress((void**)&vh, g_vh);
    cudaGetSymbolAddress((void**)&qh, g_qh);
    cudaGetSymbolAddress((void**)&co, g_co);
    cudaGetSymbolAddress((void**)&query, g_query);
    cudaGetSymbolAddress((void**)&cfn, g_cfn);
    cudaGetSymbolAddress((void**)&cff, g_cff);

    detect_mask_kernel<<<1, 1>>>((const unsigned int*)mask);
    copy_kernel<<<(B_*N_*D_ + 255) / 256, 256>>>(x, h, B_*N_*D_);

    // -------- particle transformer layers --------
    for (int l = 0; l < L_; l++) {
        const float* wq = p_wq + (long)l * D_ * D_;
        const float* wk = p_wk + (long)l * D_ * D_;
        const float* wv = p_wv + (long)l * D_ * D_;
        const float* wo = p_wo + (long)l * D_ * D_;
        const float* w1 = p_w1 + (long)l * D_ * F_;
        const float* w2 = p_w2 + (long)l * F_ * D_;

        ln_kernel<<<B_*N_, 128>>>(h, hn, p_ln1_g + (long)l * D_, p_ln1_b + (long)l * D_);
        launch_gemm_simple(hn, wq, q, B_*N_, D_, D_, D_, D_, D_, nullptr, nullptr, 0, 0);
        launch_gemm_simple(hn, wk, k, B_*N_, D_, D_, D_, D_, D_, nullptr, nullptr, 0, 0);
        launch_gemm_simple(hn, wv, v, B_*N_, D_, D_, D_, D_, D_, nullptr, nullptr, 0, 0);

        // scores: S[b,h,qi,ki] = sum_d Q[b,qi,h,d]*K[b,ki,h,d]  (scale/bias/mask in softmax)
        launch_gemm(q, k, s, N_, N_, DH_, D_, D_, N_,
                    nullptr, nullptr, 0, 0,
                    B_*H_, H_,
                    (long)N_*D_, DH_, (long)N_*D_, DH_, (long)H_*N_*N_, (long)N_*N_,
                    0, 0, true);

        attn_softmax_kernel<<<B_*H_*N_, 256>>>(s, inter, mask);

        // O = A @ V  -> ao[b, qi, h*64+dh]
        launch_gemm(s, v, ao, N_, DH_, N_, N_, D_, D_,
                    nullptr, nullptr, 0, 0,
                    B_*H_, H_,
                    (long)H_*N_*N_, (long)N_*N_, (long)N_*D_, DH_, (long)N_*D_, DH_,
                    0, 0, false);

        // h = h + ao @ Wo
        launch_gemm_simple(ao, wo, h, B_*N_, D_, D_, D_, D_, D_, nullptr, h, D_, 0);

        // FFN
        ln_kernel<<<B_*N_, 128>>>(h, hn, p_ln2_g + (long)l * D_, p_ln2_b + (long)l * D_);
        launch_gemm_simple(hn, w1, t, B_*N_, F_, D_, D_, F_, F_,
                           p_b1 + (long)l * F_, nullptr, 0, 1);
        launch_gemm_simple(t, w2, h, B_*N_, D_, F_, F_, D_, D_,
                           p_b2 + (long)l * D_, h, D_, 0);
    }

    // -------- class attention layers --------
    bcast_token_kernel<<<(B_*D_ + 255) / 256, 256>>>(ctok);
    for (int l = 0; l < LC_; l++) {
        ln_cat_kernel<<<B_*NTOK_, 128>>>(query, h, cn,
                                         c_ln1_g + (long)l * D_, c_ln1_b + (long)l * D_);
        // qh from RAW query (as in source)
        launch_gemm_simple(query, c_qk + (long)l * D_ * D_, qh, B_, D_, D_, D_, D_, D_,
                           c_qb + (long)l * D_, nullptr, 0, 0);
        launch_gemm_simple(cn, c_kk + (long)l * D_ * D_, kh, B_*NTOK_, D_, D_, D_, D_, D_,
                           c_kb + (long)l * D_, nullptr, 0, 0);
        launch_gemm_simple(cn, c_vk + (long)l * D_ * D_, vh, B_*NTOK_, D_, D_, D_, D_, D_,
                           c_vb + (long)l * D_, nullptr, 0, 0);

        cattn_kernel<<<B_*H_, 128>>>(qh, kh, vh, co, mask);

        // query = query + co @ c_ok + c_ob
        launch_gemm_simple(co, c_ok + (long)l * D_ * D_, query, B_, D_, D_, D_, D_, D_,
                           c_ob + (long)l * D_, query, D_, 0);

        ln_kernel<<<B_, 128>>>(query, cfn, c_ln2_g + (long)l * D_, c_ln2_b + (long)l * D_);
        launch_gemm_simple(cfn, c_w1 + (long)l * D_ * F_, cff, B_, F_, D_, D_, F_, F_,
                           c_b1 + (long)l * F_, nullptr, 0, 1);
        launch_gemm_simple(cff, c_w2 + (long)l * F_ * D_, query, B_, D_, F_, F_, D_, D_,
                           c_b2 + (long)l * D_, query, D_, 0);
    }

    copy_kernel<<<(B_*D_ + 255) / 256, 256>>>(query, (float*)d_out, B_*D_);
}

// round 2
// speedup vs baseline: 2.7962x; 2.7962x over previous
#include <cuda_runtime.h>
#include <math.h>

#define B_ 32
#define N_ 256
#define D_ 512
#define H_ 8
#define DH_ 64
#define F_ 2048
#define L_ 8
#define LC_ 2
#define NTOK_ 257

// ---------------- scratch (device globals; no allocation allowed) ----------------
static __device__ float g_h [B_*N_*D_];
static __device__ float g_hn[B_*N_*D_];
static __device__ float g_q [B_*N_*D_];
static __device__ float g_k [B_*N_*D_];
static __device__ float g_v [B_*N_*D_];
static __device__ float g_ao[B_*N_*D_];
static __device__ float g_s [B_*H_*N_*N_];
static __device__ float g_t [B_*N_*F_];
static __device__ float g_cn[B_*NTOK_*D_];
static __device__ float g_kh[B_*NTOK_*D_];
static __device__ float g_vh[B_*NTOK_*D_];
static __device__ float g_qh[B_*D_];
static __device__ float g_co[B_*D_];
static __device__ float g_query[B_*D_];
static __device__ float g_cfn[B_*D_];
static __device__ float g_cff[B_*F_];
static __device__ int   g_mask_mode;

// ---------------- mask dtype detection ----------------
__global__ void detect_mask_kernel(const unsigned int* m) {
    unsigned int w = m[0];
    int mode = 0;                        // int32
    if (w == 0x01010101u) mode = 1;      // uint8/bool
    else if (w == 0x3F800000u) mode = 2; // float32
    g_mask_mode = mode;
}

__device__ __forceinline__ bool mget(const void* m, int idx) {
    int mode = g_mask_mode;
    if (mode == 1) return ((const unsigned char*)m)[idx] != 0;
    if (mode == 2) return ((const float*)m)[idx] != 0.0f;
    return ((const int*)m)[idx] != 0;
}

// ---------------- tiny utility kernels ----------------
__global__ void copy_kernel(const float* __restrict__ src, float* __restrict__ dst, int n) {
    int i = blockIdx.x * 256 + threadIdx.x;
    if (i < n) dst[i] = src[i];
}

__global__ void bcast_token_kernel(const float* __restrict__ tok) {
    int i = blockIdx.x * 256 + threadIdx.x;
    if (i < B_*D_) g_query[i] = tok[i % D_];
}

// ---------------- LayerNorm (eps = 1e-3) ----------------
__device__ __forceinline__ void ln_row(const float* __restrict__ x, float* __restrict__ o,
                                       const float* __restrict__ g, const float* __restrict__ bb) {
    int tid = threadIdx.x; // 128 threads
    float s = 0.f, s2 = 0.f;
    #pragma unroll
    for (int i = tid; i < D_; i += 128) { float v = x[i]; s += v; s2 += v * v; }
    __shared__ float sh[8];
    #pragma unroll
    for (int off = 16; off; off >>= 1) {
        s  += __shfl_xor_sync(0xffffffffu, s,  off);
        s2 += __shfl_xor_sync(0xffffffffu, s2, off);
    }
    if ((tid & 31) == 0) { sh[tid >> 5] = s; sh[4 + (tid >> 5)] = s2; }
    __syncthreads();
    s  = sh[0] + sh[1] + sh[2] + sh[3];
    s2 = sh[4] + sh[5] + sh[6] + sh[7];
    float mean = s * (1.f / D_);
    float var  = s2 * (1.f / D_) - mean * mean;
    float r = rsqrtf(var + 1e-3f);
    #pragma unroll
    for (int i = tid; i < D_; i += 128) o[i] = (x[i] - mean) * r * g[i] + bb[i];
}

__global__ void ln_kernel(const float* __restrict__ in, float* __restrict__ out,
                          const float* __restrict__ g, const float* __restrict__ b) {
    long row = blockIdx.x;
    ln_row(in + row * D_, out + row * D_, g, b);
}

__global__ void ln_cat_kernel(const float* __restrict__ query, const float* __restrict__ h,
                              float* __restrict__ out,
                              const float* __restrict__ g, const float* __restrict__ b) {
    int row = blockIdx.x;
    int bb = row / NTOK_, sidx = row % NTOK_;
    const float* x = (sidx == 0) ? (query + (long)bb * D_)
                                 : (h + ((long)(bb * N_) + sidx - 1) * D_);
    ln_row(x, out + (long)row * D_, g, b);
}

// ---------------- TF32 tensor-core GEMM ----------------
__device__ __forceinline__ unsigned f2tf(float f) {
    unsigned u; asm("cvt.rna.tf32.f32 %0, %1;" : "=r"(u) : "f"(f)); return u;
}

__device__ __forceinline__ void mma_tf32(float c[4], const unsigned a[4], const unsigned b[2]) {
    asm volatile(
        "mma.sync.aligned.m16n8k8.row.col.f32.tf32.tf32.f32 "
        "{%0,%1,%2,%3}, {%4,%5,%6,%7}, {%8,%9}, {%0,%1,%2,%3};\n"
        : "+f"(c[0]), "+f"(c[1]), "+f"(c[2]), "+f"(c[3])
        : "r"(a[0]), "r"(a[1]), "r"(a[2]), "r"(a[3]), "r"(b[0]), "r"(b[1]));
}

// BM=128, BN=128, BK=16, 256 threads (8 warps = 2Mx4N, warp tile 64x32)
// smem stride 136 -> bank = 8*k + m (mod 32): conflict-free fragment loads.
template<int TRANSB>
__global__ void __launch_bounds__(256) gemm_tc(
    const float* __restrict__ A, const float* __restrict__ Bm, float* __restrict__ C,
    int M, int Nn, int K, int lda, int ldb, int ldc,
    int zdiv, long sA1, long sA2, long sB1, long sB2, long sC1, long sC2,
    const float* __restrict__ bias, const float* __restrict__ res, int ldr,
    long sR1, long sR2, int act)
{
    __shared__ unsigned As[2][16 * 136];
    __shared__ unsigned Bs[2][16 * 136];

    int z = blockIdx.z;
    long z1 = z / zdiv, z2 = z % zdiv;
    A  += z1 * sA1 + z2 * sA2;
    Bm += z1 * sB1 + z2 * sB2;
    C  += z1 * sC1 + z2 * sC2;
    if (res) res += z1 * sR1 + z2 * sR2;

    const int tid  = threadIdx.x;
    const int wid  = tid >> 5, lane = tid & 31;
    const int wM   = wid >> 2, wN = wid & 3;       // 2 x 4 warps
    const int g    = lane >> 2, tg = lane & 3;
    const int m0   = blockIdx.y * 128, n0 = blockIdx.x * 128;

    float acc[4][4][4];
    #pragma unroll
    for (int i = 0; i < 4; i++)
        #pragma unroll
        for (int j = 0; j < 4; j++)
            #pragma unroll
            for (int r = 0; r < 4; r++) acc[i][j][r] = 0.f;

    float4 ra[2], rb[2];

    // ---- global load helpers ----
    auto loadA = [&](int k0) {
        #pragma unroll
        for (int i = 0; i < 2; i++) {
            int f = tid + i * 256;
            int row = f >> 2, c4 = (f & 3) << 2;
            ra[i] = make_float4(0.f, 0.f, 0.f, 0.f);
            if (m0 + row < M)
                ra[i] = *(const float4*)(A + (long)(m0 + row) * lda + k0 + c4);
        }
        if (TRANSB) {
            #pragma unroll
            for (int i = 0; i < 2; i++) {
                int f = tid + i * 256;
                int row = f >> 2, c4 = (f & 3) << 2;
                rb[i] = make_float4(0.f, 0.f, 0.f, 0.f);
                if (n0 + row < Nn)
                    rb[i] = *(const float4*)(Bm + (long)(n0 + row) * ldb + k0 + c4);
            }
        } else {
            #pragma unroll
            for (int i = 0; i < 2; i++) {
                int f = tid + i * 256;
                int row = f >> 5, c4 = (f & 31) << 2;
                rb[i] = make_float4(0.f, 0.f, 0.f, 0.f);
                if (n0 + c4 < Nn)
                    rb[i] = *(const float4*)(Bm + (long)(k0 + row) * ldb + n0 + c4);
            }
        }
    };
    auto storeSm = [&](int buf) {
        unsigned* as = As[buf];
        unsigned* bs = Bs[buf];
        #pragma unroll
        for (int i = 0; i < 2; i++) {
            int f = tid + i * 256;
            int row = f >> 2, c4 = (f & 3) << 2;
            as[(c4 + 0) * 136 + row] = f2tf(ra[i].x);
            as[(c4 + 1) * 136 + row] = f2tf(ra[i].y);
            as[(c4 + 2) * 136 + row] = f2tf(ra[i].z);
            as[(c4 + 3) * 136 + row] = f2tf(ra[i].w);
        }
        if (TRANSB) {
            #pragma unroll
            for (int i = 0; i < 2; i++) {
                int f = tid + i * 256;
                int row = f >> 2, c4 = (f & 3) << 2;
                bs[(c4 + 0) * 136 + row] = f2tf(rb[i].x);
                bs[(c4 + 1) * 136 + row] = f2tf(rb[i].y);
                bs[(c4 + 2) * 136 + row] = f2tf(rb[i].z);
                bs[(c4 + 3) * 136 + row] = f2tf(rb[i].w);
            }
        } else {
            #pragma unroll
            for (int i = 0; i < 2; i++) {
                int f = tid + i * 256;
                int row = f >> 5, c4 = (f & 31) << 2;
                uint4 u;
                u.x = f2tf(rb[i].x); u.y = f2tf(rb[i].y);
                u.z = f2tf(rb[i].z); u.w = f2tf(rb[i].w);
                *(uint4*)(bs + row * 136 + c4) = u;
            }
        }
    };
    auto compute = [&](int buf) {
        const unsigned* as = As[buf];
        const unsigned* bs = Bs[buf];
        #pragma unroll
        for (int ks = 0; ks < 16; ks += 8) {
            unsigned af[4][4], bf[4][2];
            #pragma unroll
            for (int mt = 0; mt < 4; mt++) {
                int m = wM * 64 + mt * 16 + g;
                af[mt][0] = as[(ks + tg) * 136 + m];
                af[mt][1] = as[(ks + tg) * 136 + m + 8];
                af[mt][2] = as[(ks + tg + 4) * 136 + m];
                af[mt][3] = as[(ks + tg + 4) * 136 + m + 8];
            }
            #pragma unroll
            for (int nt = 0; nt < 4; nt++) {
                int n = wN * 32 + nt * 8 + g;
                bf[nt][0] = bs[(ks + tg) * 136 + n];
                bf[nt][1] = bs[(ks + tg + 4) * 136 + n];
            }
            #pragma unroll
            for (int mt = 0; mt < 4; mt++)
                #pragma unroll
                for (int nt = 0; nt < 4; nt++)
                    mma_tf32(acc[mt][nt], af[mt], bf[nt]);
        }
    };

    // ---- pipelined main loop ----
    loadA(0);
    storeSm(0);
    __syncthreads();
    int cur = 0;
    for (int k0 = 0; k0 < K; k0 += 16) {
        bool nxt = (k0 + 16) < K;
        if (nxt) loadA(k0 + 16);
        compute(cur);
        if (nxt) {
            storeSm(cur ^ 1);
            __syncthreads();
            cur ^= 1;
        }
    }

    // ---- epilogue ----
    #pragma unroll
    for (int mt = 0; mt < 4; mt++) {
        #pragma unroll
        for (int nt = 0; nt < 4; nt++) {
            int m = m0 + wM * 64 + mt * 16 + g;
            int n = n0 + wN * 32 + nt * 8 + tg * 2;
            if (n >= Nn) continue;
            float bx = 0.f, by = 0.f;
            if (bias) { bx = bias[n]; by = bias[n + 1]; }
            #pragma unroll
            for (int half = 0; half < 2; half++) {
                int mm = m + half * 8;
                if (mm >= M) continue;
                float2 v = make_float2(acc[mt][nt][half * 2], acc[mt][nt][half * 2 + 1]);
                if (bias) { v.x += bx; v.y += by; }
                if (act) {
                    v.x = 0.5f * v.x * (1.f + erff(v.x * 0.70710678118654752f));
                    v.y = 0.5f * v.y * (1.f + erff(v.y * 0.70710678118654752f));
                }
                if (res) {
                    float2 r = *(const float2*)(res + (long)mm * ldr + n);
                    v.x += r.x; v.y += r.y;
                }
                *(float2*)(C + (long)mm * ldc + n) = v;
            }
        }
    }
}

// ---------------- masked softmax with interaction bias (coalesced) ----------------
// One block per (b, qi); each thread owns key k and reads its 8 h-values of
// inter contiguously (two float4), then loops over the 8 heads' score rows.
__global__ void attn_softmax2(float* __restrict__ s, const float* __restrict__ inter,
                              const void* __restrict__ mask) {
    int row = blockIdx.x;           // b*N + qi
    int qi = row % N_, b = row / N_;
    int k = threadIdx.x;            // 256 threads
    int lane = k & 31, w = k >> 5;
    bool qm = mget(mask, b * N_ + qi);
    bool km = mget(mask, b * N_ + k);
    float madd = (qm && km) ? 0.f : -1e9f;
    const float4* ip = (const float4*)(inter + ((long)row * N_ + k) * H_);
    float4 i0 = ip[0], i1 = ip[1];
    float iv[8] = {i0.x, i0.y, i0.z, i0.w, i1.x, i1.y, i1.z, i1.w};
    __shared__ float red[8];
    #pragma unroll
    for (int h = 0; h < H_; h++) {
        float* srow = s + (((long)b * H_ + h) * N_ + qi) * N_;
        float v = srow[k] * 0.125f + iv[h] + madd;
        float m = v;
        #pragma unroll
        for (int off = 16; off; off >>= 1) m = fmaxf(m, __shfl_xor_sync(0xffffffffu, m, off));
        if (lane == 0) red[w] = m;
        __syncthreads();
        m = fmaxf(fmaxf(fmaxf(red[0], red[1]), fmaxf(red[2], red[3])),
                  fmaxf(fmaxf(red[4], red[5]), fmaxf(red[6], red[7])));
        float e = expf(v - m);
        float sm = e;
        #pragma unroll
        for (int off = 16; off; off >>= 1) sm += __shfl_xor_sync(0xffffffffu, sm, off);
        __syncthreads();
        if (lane == 0) red[w] = sm;
        __syncthreads();
        sm = red[0] + red[1] + red[2] + red[3] + red[4] + red[5] + red[6] + red[7];
        srow[k] = e / sm;
        __syncthreads();
    }
}

// ---------------- class attention core (per b,h) ----------------
__global__ void cattn_kernel(const float* __restrict__ qh, const float* __restrict__ kh,
                             const float* __restrict__ vh, float* __restrict__ co,
                             const void* __restrict__ mask) {
    int z = blockIdx.x;
    int b = z / H_, h = z % H_;
    int tid = threadIdx.x; // 128 threads
    __shared__ float a[NTOK_];
    __shared__ float red[4];
    const float* qv = qh + (long)b * D_ + h * DH_;
    float lmax = -3.0e38f;
    for (int sidx = tid; sidx < NTOK_; sidx += 128) {
        const float* kv = kh + ((long)(b * NTOK_ + sidx)) * D_ + h * DH_;
        float sc = 0.f;
        #pragma unroll
        for (int d = 0; d < DH_; d++) sc += qv[d] * kv[d];
        sc = sc * 0.125f + ((sidx == 0 || mget(mask, b * N_ + sidx - 1)) ? 0.f : -1e9f);
        a[sidx] = sc;
        lmax = fmaxf(lmax, sc);
    }
    #pragma unroll
    for (int off = 16; off; off >>= 1) lmax = fmaxf(lmax, __shfl_xor_sync(0xffffffffu, lmax, off));
    if ((tid & 31) == 0) red[tid >> 5] = lmax;
    __syncthreads();
    float m = fmaxf(fmaxf(red[0], red[1]), fmaxf(red[2], red[3]));
    __syncthreads();
    float lsum = 0.f;
    for (int sidx = tid; sidx < NTOK_; sidx += 128) {
        float e = expf(a[sidx] - m);
        a[sidx] = e;
        lsum += e;
    }
    #pragma unroll
    for (int off = 16; off; off >>= 1) lsum += __shfl_xor_sync(0xffffffffu, lsum, off);
    if ((tid & 31) == 0) red[tid >> 5] = lsum;
    __syncthreads();
    float inv = 1.f / (red[0] + red[1] + red[2] + red[3]);
    if (tid < DH_) {
        float o = 0.f;
        for (int sidx = 0; sidx < NTOK_; sidx++)
            o += a[sidx] * vh[((long)(b * NTOK_ + sidx)) * D_ + h * DH_ + tid];
        co[(long)b * D_ + h * DH_ + tid] = o * inv;
    }
}

// ---------------- host-side launch helpers ----------------
static void launch_gemm(const float* A, const float* Bm, float* C,
                        int M, int Nn, int K, int lda, int ldb, int ldc,
                        const float* bias, const float* res, int ldr, int act,
                        int nz, int zdiv,
                        long sA1, long sA2, long sB1, long sB2, long sC1, long sC2,
                        long sR1, long sR2, bool transb) {
    dim3 grid((Nn + 127) / 128, (M + 127) / 128, nz);
    if (transb)
        gemm_tc<1><<<grid, 256>>>(A, Bm, C, M, Nn, K, lda, ldb, ldc,
                                  zdiv, sA1, sA2, sB1, sB2, sC1, sC2,
                                  bias, res, ldr, sR1, sR2, act);
    else
        gemm_tc<0><<<grid, 256>>>(A, Bm, C, M, Nn, K, lda, ldb, ldc,
                                  zdiv, sA1, sA2, sB1, sB2, sC1, sC2,
                                  bias, res, ldr, sR1, sR2, act);
}

static void launch_gemm_simple(const float* A, const float* Bm, float* C,
                               int M, int Nn, int K, int lda, int ldb, int ldc,
                               const float* bias, const float* res, int ldr, int act) {
    launch_gemm(A, Bm, C, M, Nn, K, lda, ldb, ldc, bias, res, ldr, act,
                1, 1, 0, 0, 0, 0, 0, 0, 0, 0, false);
}

extern "C" void kernel_launch(void* const* d_in, const int* in_sizes, int n_in,
                              void* d_out, int out_size) {
    const float* x       = (const float*)d_in[0];
    const float* inter   = (const float*)d_in[1];
    const float* ctok    = (const float*)d_in[2];
    const float* p_ln1_g = (const float*)d_in[3];
    const float* p_ln1_b = (const float*)d_in[4];
    const float* p_wq    = (const float*)d_in[5];
    const float* p_wk    = (const float*)d_in[6];
    const float* p_wv    = (const float*)d_in[7];
    const float* p_wo    = (const float*)d_in[8];
    const float* p_ln2_g = (const float*)d_in[9];
    const float* p_ln2_b = (const float*)d_in[10];
    const float* p_w1    = (const float*)d_in[11];
    const float* p_b1    = (const float*)d_in[12];
    const float* p_w2    = (const float*)d_in[13];
    const float* p_b2    = (const float*)d_in[14];
    const float* c_ln1_g = (const float*)d_in[15];
    const float* c_ln1_b = (const float*)d_in[16];
    const float* c_qk    = (const float*)d_in[17];
    const float* c_qb    = (const float*)d_in[18];
    const float* c_kk    = (const float*)d_in[19];
    const float* c_kb    = (const float*)d_in[20];
    const float* c_vk    = (const float*)d_in[21];
    const float* c_vb    = (const float*)d_in[22];
    const float* c_ok    = (const float*)d_in[23];
    const float* c_ob    = (const float*)d_in[24];
    const float* c_ln2_g = (const float*)d_in[25];
    const float* c_ln2_b = (const float*)d_in[26];
    const float* c_w1    = (const float*)d_in[27];
    const float* c_b1    = (const float*)d_in[28];
    const float* c_w2    = (const float*)d_in[29];
    const float* c_b2    = (const float*)d_in[30];
    const void*  mask    = d_in[31];

    float *h, *hn, *q, *k, *v, *ao, *s, *t, *cn, *kh, *vh, *qh, *co, *query, *cfn, *cff;
    cudaGetSymbolAddress((void**)&h,  g_h);
    cudaGetSymbolAddress((void**)&hn, g_hn);
    cudaGetSymbolAddress((void**)&q,  g_q);
    cudaGetSymbolAddress((void**)&k,  g_k);
    cudaGetSymbolAddress((void**)&v,  g_v);
    cudaGetSymbolAddress((void**)&ao, g_ao);
    cudaGetSymbolAddress((void**)&s,  g_s);
    cudaGetSymbolAddress((void**)&t,  g_t);
    cudaGetSymbolAddress((void**)&cn, g_cn);
    cudaGetSymbolAddress((void**)&kh, g_kh);
    cudaGetSymbolAddress((void**)&vh, g_vh);
    cudaGetSymbolAddress((void**)&qh, g_qh);
    cudaGetSymbolAddress((void**)&co, g_co);
    cudaGetSymbolAddress((void**)&query, g_query);
    cudaGetSymbolAddress((void**)&cfn, g_cfn);
    cudaGetSymbolAddress((void**)&cff, g_cff);

    detect_mask_kernel<<<1, 1>>>((const unsigned int*)mask);
    copy_kernel<<<(B_*N_*D_ + 255) / 256, 256>>>(x, h, B_*N_*D_);

    // -------- particle transformer layers --------
    for (int l = 0; l < L_; l++) {
        const float* wq = p_wq + (long)l * D_ * D_;
        const float* wk = p_wk + (long)l * D_ * D_;
        const float* wv = p_wv + (long)l * D_ * D_;
        const float* wo = p_wo + (long)l * D_ * D_;
        const float* w1 = p_w1 + (long)l * D_ * F_;
        const float* w2 = p_w2 + (long)l * F_ * D_;

        ln_kernel<<<B_*N_, 128>>>(h, hn, p_ln1_g + (long)l * D_, p_ln1_b + (long)l * D_);
        launch_gemm_simple(hn, wq, q, B_*N_, D_, D_, D_, D_, D_, nullptr, nullptr, 0, 0);
        launch_gemm_simple(hn, wk, k, B_*N_, D_, D_, D_, D_, D_, nullptr, nullptr, 0, 0);
        launch_gemm_simple(hn, wv, v, B_*N_, D_, D_, D_, D_, D_, nullptr, nullptr, 0, 0);

        // scores S[b,h,qi,ki] = sum_d Q[b,qi,h,d]*K[b,ki,h,d]
        launch_gemm(q, k, s, N_, N_, DH_, D_, D_, N_,
                    nullptr, nullptr, 0, 0,
                    B_*H_, H_,
                    (long)N_*D_, DH_, (long)N_*D_, DH_, (long)H_*N_*N_, (long)N_*N_,
                    0, 0, true);

        attn_softmax2<<<B_*N_, 256>>>(s, inter, mask);

        // O = A @ V -> ao[b, qi, h*64+dh]
        launch_gemm(s, v, ao, N_, DH_, N_, N_, D_, D_,
                    nullptr, nullptr, 0, 0,
                    B_*H_, H_,
                    (long)H_*N_*N_, (long)N_*N_, (long)N_*D_, DH_, (long)N_*D_, DH_,
                    0, 0, false);

        // h = h + ao @ Wo
        launch_gemm_simple(ao, wo, h, B_*N_, D_, D_, D_, D_, D_, nullptr, h, D_, 0);

        // FFN
        ln_kernel<<<B_*N_, 128>>>(h, hn, p_ln2_g + (long)l * D_, p_ln2_b + (long)l * D_);
        launch_gemm_simple(hn, w1, t, B_*N_, F_, D_, D_, F_, F_,
                           p_b1 + (long)l * F_, nullptr, 0, 1);
        launch_gemm_simple(t, w2, h, B_*N_, D_, F_, F_, D_, D_,
                           p_b2 + (long)l * D_, h, D_, 0);
    }

    // -------- class attention layers --------
    bcast_token_kernel<<<(B_*D_ + 255) / 256, 256>>>(ctok);
    for (int l = 0; l < LC_; l++) {
        ln_cat_kernel<<<B_*NTOK_, 128>>>(query, h, cn,
                                         c_ln1_g + (long)l * D_, c_ln1_b + (long)l * D_);
        launch_gemm_simple(query, c_qk + (long)l * D_ * D_, qh, B_, D_, D_, D_, D_, D_,
                           c_qb + (long)l * D_, nullptr, 0, 0);
        launch_gemm_simple(cn, c_kk + (long)l * D_ * D_, kh, B_*NTOK_, D_, D_, D_, D_, D_,
                           c_kb + (long)l * D_, nullptr, 0, 0);
        launch_gemm_simple(cn, c_vk + (long)l * D_ * D_, vh, B_*NTOK_, D_, D_, D_, D_, D_,
                           c_vb + (long)l * D_, nullptr, 0, 0);

        cattn_kernel<<<B_*H_, 128>>>(qh, kh, vh, co, mask);

        launch_gemm_simple(co, c_ok + (long)l * D_ * D_, query, B_, D_, D_, D_, D_, D_,
                           c_ob + (long)l * D_, query, D_, 0);

        ln_kernel<<<B_, 128>>>(query, cfn, c_ln2_g + (long)l * D_, c_ln2_b + (long)l * D_);
        launch_gemm_simple(cfn, c_w1 + (long)l * D_ * F_, cff, B_, F_, D_, D_, F_, F_,
                           c_b1 + (long)l * F_, nullptr, 0, 1);
        launch_gemm_simple(cff, c_w2 + (long)l * F_ * D_, query, B_, D_, F_, F_, D_, D_,
                           c_b2 + (long)l * D_, query, D_, 0);
    }

    copy_kernel<<<(B_*D_ + 255) / 256, 256>>>(query, (float*)d_out, B_*D_);
}

// round 3
// speedup vs baseline: 3.0425x; 1.0881x over previous
#include <cuda_runtime.h>
#include <math.h>
#include <stdint.h>

#define B_ 32
#define N_ 256
#define D_ 512
#define H_ 8
#define DH_ 64
#define F_ 2048
#define L_ 8
#define LC_ 2
#define NTOK_ 257

// ---------------- scratch (device globals; no allocation allowed) ----------------
static __device__ float g_h [B_*N_*D_];
static __device__ float g_hn[B_*N_*D_];
static __device__ float g_q [B_*N_*D_];
static __device__ float g_k [B_*N_*D_];
static __device__ float g_v [B_*N_*D_];
static __device__ float g_ao[B_*N_*D_];
static __device__ float g_s [B_*H_*N_*N_];
static __device__ float g_t [B_*N_*F_];
static __device__ float g_cn[B_*NTOK_*D_];
static __device__ float g_kh[B_*NTOK_*D_];
static __device__ float g_vh[B_*NTOK_*D_];
static __device__ float g_qh[B_*D_];
static __device__ float g_co[B_*D_];
static __device__ float g_query[B_*D_];
static __device__ float g_cfn[B_*D_];
static __device__ float g_cff[B_*F_];
static __device__ int   g_mask_mode;

// pre-rounded (tf32) weight copies
static __device__ float g_rwq[L_*D_*D_];
static __device__ float g_rwk[L_*D_*D_];
static __device__ float g_rwv[L_*D_*D_];
static __device__ float g_rwo[L_*D_*D_];
static __device__ float g_rw1[L_*D_*F_];
static __device__ float g_rw2[L_*F_*D_];
static __device__ float g_rcqk[LC_*D_*D_];
static __device__ float g_rckk[LC_*D_*D_];
static __device__ float g_rcvk[LC_*D_*D_];
static __device__ float g_rcok[LC_*D_*D_];
static __device__ float g_rcw1[LC_*D_*F_];
static __device__ float g_rcw2[LC_*D_*F_];

// ---------------- tf32 rounding helper ----------------
__device__ __forceinline__ float tf32r(float f) {
    unsigned u; asm("cvt.rna.tf32.f32 %0, %1;" : "=r"(u) : "f"(f));
    return __uint_as_float(u);
}

__global__ void round_kernel(const float* __restrict__ src, float* __restrict__ dst, int n) {
    int i = blockIdx.x * 256 + threadIdx.x;
    if (i < n) dst[i] = tf32r(src[i]);
}

// ---------------- mask dtype detection ----------------
__global__ void detect_mask_kernel(const unsigned int* m) {
    unsigned int w = m[0];
    int mode = 0;                        // int32
    if (w == 0x01010101u) mode = 1;      // uint8/bool
    else if (w == 0x3F800000u) mode = 2; // float32
    g_mask_mode = mode;
}

__device__ __forceinline__ bool mget(const void* m, int idx) {
    int mode = g_mask_mode;
    if (mode == 1) return ((const unsigned char*)m)[idx] != 0;
    if (mode == 2) return ((const float*)m)[idx] != 0.0f;
    return ((const int*)m)[idx] != 0;
}

// ---------------- tiny utility kernels ----------------
__global__ void copy_kernel(const float* __restrict__ src, float* __restrict__ dst, int n) {
    int i = blockIdx.x * 256 + threadIdx.x;
    if (i < n) dst[i] = src[i];
}

__global__ void bcast_token_kernel(const float* __restrict__ tok) {
    int i = blockIdx.x * 256 + threadIdx.x;
    if (i < B_*D_) g_query[i] = tok[i % D_];
}

// ---------------- LayerNorm (eps = 1e-3) ----------------
__device__ __forceinline__ void ln_row(const float* __restrict__ x, float* __restrict__ o,
                                       const float* __restrict__ g, const float* __restrict__ bb,
                                       int tfr) {
    int tid = threadIdx.x; // 128 threads
    float s = 0.f, s2 = 0.f;
    #pragma unroll
    for (int i = tid; i < D_; i += 128) { float v = x[i]; s += v; s2 += v * v; }
    __shared__ float sh[8];
    #pragma unroll
    for (int off = 16; off; off >>= 1) {
        s  += __shfl_xor_sync(0xffffffffu, s,  off);
        s2 += __shfl_xor_sync(0xffffffffu, s2, off);
    }
    if ((tid & 31) == 0) { sh[tid >> 5] = s; sh[4 + (tid >> 5)] = s2; }
    __syncthreads();
    s  = sh[0] + sh[1] + sh[2] + sh[3];
    s2 = sh[4] + sh[5] + sh[6] + sh[7];
    float mean = s * (1.f / D_);
    float var  = s2 * (1.f / D_) - mean * mean;
    float r = rsqrtf(var + 1e-3f);
    #pragma unroll
    for (int i = tid; i < D_; i += 128) {
        float v = (x[i] - mean) * r * g[i] + bb[i];
        o[i] = tfr ? tf32r(v) : v;
    }
}

__global__ void ln_kernel(const float* __restrict__ in, float* __restrict__ out,
                          const float* __restrict__ g, const float* __restrict__ b, int tfr) {
    long row = blockIdx.x;
    ln_row(in + row * D_, out + row * D_, g, b, tfr);
}

__global__ void ln_cat_kernel(const float* __restrict__ query, const float* __restrict__ h,
                              float* __restrict__ out,
                              const float* __restrict__ g, const float* __restrict__ b) {
    int row = blockIdx.x;
    int bb = row / NTOK_, sidx = row % NTOK_;
    const float* x = (sidx == 0) ? (query + (long)bb * D_)
                                 : (h + ((long)(bb * N_) + sidx - 1) * D_);
    ln_row(x, out + (long)row * D_, g, b, 1);
}

// ---------------- cp.async helpers ----------------
__device__ __forceinline__ void cp16(float* smem_ptr, const float* gptr, bool pred) {
    uint32_t sa = (uint32_t)__cvta_generic_to_shared(smem_ptr);
    int sz = pred ? 16 : 0;
    asm volatile("cp.async.cg.shared.global [%0], [%1], 16, %2;\n" :: "r"(sa), "l"(gptr), "r"(sz));
}
__device__ __forceinline__ void cp_commit() {
    asm volatile("cp.async.commit_group;\n" ::: "memory");
}
template<int NN>
__device__ __forceinline__ void cp_wait() {
    asm volatile("cp.async.wait_group %0;\n" :: "n"(NN) : "memory");
}

// ---------------- TF32 tensor-core GEMM (cvt-free, 4-stage cp.async) ----------------
// Inputs must already be tf32-representable fp32 (hardware truncation = no-op).
__device__ __forceinline__ void mma_tf32(float c[4], const unsigned a[4], const unsigned b[2]) {
    asm volatile(
        "mma.sync.aligned.m16n8k8.row.col.f32.tf32.tf32.f32 "
        "{%0,%1,%2,%3}, {%4,%5,%6,%7}, {%8,%9}, {%0,%1,%2,%3};\n"
        : "+f"(c[0]), "+f"(c[1]), "+f"(c[2]), "+f"(c[3])
        : "r"(a[0]), "r"(a[1]), "r"(a[2]), "r"(a[3]), "r"(b[0]), "r"(b[1]));
}

// BM=128, BN=128, BK=16, 256 threads (8 warps = 2Mx4N, warp tile 64x32), 4 stages.
// A smem: [m][k] stride 20 (bank map 20g+tg: conflict-free)
// B smem (TRANSB=1): [n][k] stride 20; (TRANSB=0): [k][n] stride 136.
#define GSTAGES 4
#define STAGE_F 2560          // floats per (A or B) stage buffer
#define GSMEM_BYTES (2 * GSTAGES * STAGE_F * 4)   // 81920

template<int TRANSB>
__global__ void __launch_bounds__(256, 2) gemm_tc(
    const float* __restrict__ A, const float* __restrict__ Bm, float* __restrict__ C,
    int M, int Nn, int K, int lda, int ldb, int ldc,
    int zdiv, long sA1, long sA2, long sB1, long sB2, long sC1, long sC2,
    const float* __restrict__ bias, const float* __restrict__ res, int ldr,
    long sR1, long sR2, int act, int tfr)
{
    extern __shared__ float dyn[];

    int z = blockIdx.z;
    long z1 = z / zdiv, z2 = z % zdiv;
    A  += z1 * sA1 + z2 * sA2;
    Bm += z1 * sB1 + z2 * sB2;
    C  += z1 * sC1 + z2 * sC2;
    if (res) res += z1 * sR1 + z2 * sR2;

    const int tid  = threadIdx.x;
    const int wid  = tid >> 5, lane = tid & 31;
    const int wM   = wid >> 2, wN = wid & 3;   // 2 x 4 warps
    const int g    = lane >> 2, tg = lane & 3;
    const int m0   = blockIdx.y * 128, n0 = blockIdx.x * 128;

    float acc[4][4][4];
    #pragma unroll
    for (int i = 0; i < 4; i++)
        #pragma unroll
        for (int j = 0; j < 4; j++)
            #pragma unroll
            for (int r = 0; r < 4; r++) acc[i][j][r] = 0.f;

    auto load_stage = [&](int buf, int k0) {
        {   // A: 128 rows x 16 floats, row = tid>>1, 2x16B chunks
            int row = tid >> 1;
            int off = (tid & 1) * 8;
            bool p = (m0 + row) < M;
            const float* gp = p ? (A + (long)(m0 + row) * lda + k0 + off) : A;
            float* sp = dyn + buf * STAGE_F + row * 20 + off;
            cp16(sp,     gp,     p);
            cp16(sp + 4, gp + 4, p);
        }
        if (TRANSB) {
            int row = tid >> 1;
            int off = (tid & 1) * 8;
            bool p = (n0 + row) < Nn;
            const float* gp = p ? (Bm + (long)(n0 + row) * ldb + k0 + off) : Bm;
            float* sp = dyn + (GSTAGES + buf) * STAGE_F + row * 20 + off;
            cp16(sp,     gp,     p);
            cp16(sp + 4, gp + 4, p);
        } else {
            int row = tid >> 4;              // 0..15 (k)
            int off = (tid & 15) * 8;        // 0..120 (n)
            bool p0 = (n0 + off) < Nn;
            bool p1 = (n0 + off + 4) < Nn;
            const float* gp = Bm + (long)(k0 + row) * ldb + n0 + off;
            float* sp = dyn + (GSTAGES + buf) * STAGE_F + row * 136 + off;
            cp16(sp,     p0 ? gp     : Bm, p0);
            cp16(sp + 4, p1 ? gp + 4 : Bm, p1);
        }
    };

    auto compute = [&](int buf) {
        const float* As = dyn + buf * STAGE_F;
        const float* Bs = dyn + (GSTAGES + buf) * STAGE_F;
        #pragma unroll
        for (int ks = 0; ks < 16; ks += 8) {
            unsigned af[4][4], bf[4][2];
            #pragma unroll
            for (int mt = 0; mt < 4; mt++) {
                int m = wM * 64 + mt * 16 + g;
                af[mt][0] = __float_as_uint(As[(m    ) * 20 + ks + tg    ]);
                af[mt][1] = __float_as_uint(As[(m + 8) * 20 + ks + tg    ]);
                af[mt][2] = __float_as_uint(As[(m    ) * 20 + ks + tg + 4]);
                af[mt][3] = __float_as_uint(As[(m + 8) * 20 + ks + tg + 4]);
            }
            #pragma unroll
            for (int nt = 0; nt < 4; nt++) {
                int n = wN * 32 + nt * 8 + g;
                if (TRANSB) {
                    bf[nt][0] = __float_as_uint(Bs[n * 20 + ks + tg    ]);
                    bf[nt][1] = __float_as_uint(Bs[n * 20 + ks + tg + 4]);
                } else {
                    bf[nt][0] = __float_as_uint(Bs[(ks + tg    ) * 136 + n]);
                    bf[nt][1] = __float_as_uint(Bs[(ks + tg + 4) * 136 + n]);
                }
            }
            #pragma unroll
            for (int mt = 0; mt < 4; mt++)
                #pragma unroll
                for (int nt = 0; nt < 4; nt++)
                    mma_tf32(acc[mt][nt], af[mt], bf[nt]);
        }
    };

    const int KT = K >> 4;
    // prologue: prefetch first GSTAGES-1 stages
    #pragma unroll
    for (int s = 0; s < GSTAGES - 1; s++) {
        if (s < KT) load_stage(s, s * 16);
        cp_commit();
    }
    for (int kt = 0; kt < KT; kt++) {
        cp_wait<GSTAGES - 2>();
        __syncthreads();
        int pf = kt + GSTAGES - 1;
        if (pf < KT) load_stage(pf & (GSTAGES - 1), pf * 16);
        cp_commit();
        compute(kt & (GSTAGES - 1));
    }
    cp_wait<0>();

    // ---- epilogue ----
    #pragma unroll
    for (int mt = 0; mt < 4; mt++) {
        #pragma unroll
        for (int nt = 0; nt < 4; nt++) {
            int m = m0 + wM * 64 + mt * 16 + g;
            int n = n0 + wN * 32 + nt * 8 + tg * 2;
            if (n >= Nn) continue;
            float bx = 0.f, by = 0.f;
            if (bias) { bx = bias[n]; by = bias[n + 1]; }
            #pragma unroll
            for (int half = 0; half < 2; half++) {
                int mm = m + half * 8;
                if (mm >= M) continue;
                float2 v = make_float2(acc[mt][nt][half * 2], acc[mt][nt][half * 2 + 1]);
                if (bias) { v.x += bx; v.y += by; }
                if (act) {
                    v.x = 0.5f * v.x * (1.f + erff(v.x * 0.70710678118654752f));
                    v.y = 0.5f * v.y * (1.f + erff(v.y * 0.70710678118654752f));
                }
                if (res) {
                    float2 r = *(const float2*)(res + (long)mm * ldr + n);
                    v.x += r.x; v.y += r.y;
                }
                if (tfr) { v.x = tf32r(v.x); v.y = tf32r(v.y); }
                *(float2*)(C + (long)mm * ldc + n) = v;
            }
        }
    }
}

// ---------------- masked softmax with interaction bias (coalesced) ----------------
__global__ void attn_softmax2(float* __restrict__ s, const float* __restrict__ inter,
                              const void* __restrict__ mask) {
    int row = blockIdx.x;           // b*N + qi
    int qi = row % N_, b = row / N_;
    int k = threadIdx.x;            // 256 threads
    int lane = k & 31, w = k >> 5;
    bool qm = mget(mask, b * N_ + qi);
    bool km = mget(mask, b * N_ + k);
    float madd = (qm && km) ? 0.f : -1e9f;
    const float4* ip = (const float4*)(inter + ((long)row * N_ + k) * H_);
    float4 i0 = ip[0], i1 = ip[1];
    float iv[8] = {i0.x, i0.y, i0.z, i0.w, i1.x, i1.y, i1.z, i1.w};
    __shared__ float red[8];
    #pragma unroll
    for (int h = 0; h < H_; h++) {
        float* srow = s + (((long)b * H_ + h) * N_ + qi) * N_;
        float v = srow[k] * 0.125f + iv[h] + madd;
        float m = v;
        #pragma unroll
        for (int off = 16; off; off >>= 1) m = fmaxf(m, __shfl_xor_sync(0xffffffffu, m, off));
        if (lane == 0) red[w] = m;
        __syncthreads();
        m = fmaxf(fmaxf(fmaxf(red[0], red[1]), fmaxf(red[2], red[3])),
                  fmaxf(fmaxf(red[4], red[5]), fmaxf(red[6], red[7])));
        float e = expf(v - m);
        float sm = e;
        #pragma unroll
        for (int off = 16; off; off >>= 1) sm += __shfl_xor_sync(0xffffffffu, sm, off);
        __syncthreads();
        if (lane == 0) red[w] = sm;
        __syncthreads();
        sm = red[0] + red[1] + red[2] + red[3] + red[4] + red[5] + red[6] + red[7];
        srow[k] = tf32r(e / sm);
        __syncthreads();
    }
}

// ---------------- class attention core (per b,h) ----------------
__global__ void cattn_kernel(const float* __restrict__ qh, const float* __restrict__ kh,
                             const float* __restrict__ vh, float* __restrict__ co,
                             const void* __restrict__ mask) {
    int z = blockIdx.x;
    int b = z / H_, h = z % H_;
    int tid = threadIdx.x; // 128 threads
    __shared__ float a[NTOK_];
    __shared__ float red[4];
    const float* qv = qh + (long)b * D_ + h * DH_;
    float lmax = -3.0e38f;
    for (int sidx = tid; sidx < NTOK_; sidx += 128) {
        const float* kv = kh + ((long)(b * NTOK_ + sidx)) * D_ + h * DH_;
        float sc = 0.f;
        #pragma unroll
        for (int d = 0; d < DH_; d++) sc += qv[d] * kv[d];
        sc = sc * 0.125f + ((sidx == 0 || mget(mask, b * N_ + sidx - 1)) ? 0.f : -1e9f);
        a[sidx] = sc;
        lmax = fmaxf(lmax, sc);
    }
    #pragma unroll
    for (int off = 16; off; off >>= 1) lmax = fmaxf(lmax, __shfl_xor_sync(0xffffffffu, lmax, off));
    if ((tid & 31) == 0) red[tid >> 5] = lmax;
    __syncthreads();
    float m = fmaxf(fmaxf(red[0], red[1]), fmaxf(red[2], red[3]));
    __syncthreads();
    float lsum = 0.f;
    for (int sidx = tid; sidx < NTOK_; sidx += 128) {
        float e = expf(a[sidx] - m);
        a[sidx] = e;
        lsum += e;
    }
    #pragma unroll
    for (int off = 16; off; off >>= 1) lsum += __shfl_xor_sync(0xffffffffu, lsum, off);
    if ((tid & 31) == 0) red[tid >> 5] = lsum;
    __syncthreads();
    float inv = 1.f / (red[0] + red[1] + red[2] + red[3]);
    if (tid < DH_) {
        float o = 0.f;
        for (int sidx = 0; sidx < NTOK_; sidx++)
            o += a[sidx] * vh[((long)(b * NTOK_ + sidx)) * D_ + h * DH_ + tid];
        co[(long)b * D_ + h * DH_ + tid] = tf32r(o * inv);
    }
}

// ---------------- host-side launch helpers ----------------
static void launch_gemm(const float* A, const float* Bm, float* C,
                        int M, int Nn, int K, int lda, int ldb, int ldc,
                        const float* bias, const float* res, int ldr, int act, int tfr,
                        int nz, int zdiv,
                        long sA1, long sA2, long sB1, long sB2, long sC1, long sC2,
                        long sR1, long sR2, bool transb) {
    dim3 grid((Nn + 127) / 128, (M + 127) / 128, nz);
    if (transb)
        gemm_tc<1><<<grid, 256, GSMEM_BYTES>>>(A, Bm, C, M, Nn, K, lda, ldb, ldc,
                                               zdiv, sA1, sA2, sB1, sB2, sC1, sC2,
                                               bias, res, ldr, sR1, sR2, act, tfr);
    else
        gemm_tc<0><<<grid, 256, GSMEM_BYTES>>>(A, Bm, C, M, Nn, K, lda, ldb, ldc,
                                               zdiv, sA1, sA2, sB1, sB2, sC1, sC2,
                                               bias, res, ldr, sR1, sR2, act, tfr);
}

static void launch_gemm_simple(const float* A, const float* Bm, float* C,
                               int M, int Nn, int K, int lda, int ldb, int ldc,
                               const float* bias, const float* res, int ldr, int act, int tfr) {
    launch_gemm(A, Bm, C, M, Nn, K, lda, ldb, ldc, bias, res, ldr, act, tfr,
                1, 1, 0, 0, 0, 0, 0, 0, 0, 0, false);
}

extern "C" void kernel_launch(void* const* d_in, const int* in_sizes, int n_in,
                              void* d_out, int out_size) {
    const float* x       = (const float*)d_in[0];
    const float* inter   = (const float*)d_in[1];
    const float* ctok    = (const float*)d_in[2];
    const float* p_ln1_g = (const float*)d_in[3];
    const float* p_ln1_b = (const float*)d_in[4];
    const float* p_wq    = (const float*)d_in[5];
    const float* p_wk    = (const float*)d_in[6];
    const float* p_wv    = (const float*)d_in[7];
    const float* p_wo    = (const float*)d_in[8];
    const float* p_ln2_g = (const float*)d_in[9];
    const float* p_ln2_b = (const float*)d_in[10];
    const float* p_w1    = (const float*)d_in[11];
    const float* p_b1    = (const float*)d_in[12];
    const float* p_w2    = (const float*)d_in[13];
    const float* p_b2    = (const float*)d_in[14];
    const float* c_ln1_g = (const float*)d_in[15];
    const float* c_ln1_b = (const float*)d_in[16];
    const float* c_qk    = (const float*)d_in[17];
    const float* c_qb    = (const float*)d_in[18];
    const float* c_kk    = (const float*)d_in[19];
    const float* c_kb    = (const float*)d_in[20];
    const float* c_vk    = (const float*)d_in[21];
    const float* c_vb    = (const float*)d_in[22];
    const float* c_ok    = (const float*)d_in[23];
    const float* c_ob    = (const float*)d_in[24];
    const float* c_ln2_g = (const float*)d_in[25];
    const float* c_ln2_b = (const float*)d_in[26];
    const float* c_w1    = (const float*)d_in[27];
    const float* c_b1    = (const float*)d_in[28];
    const float* c_w2    = (const float*)d_in[29];
    const float* c_b2    = (const float*)d_in[30];
    const void*  mask    = d_in[31];

    // allow 80KB dynamic smem (idempotent; host-side, not captured as graph node)
    cudaFuncSetAttribute(gemm_tc<0>, cudaFuncAttributeMaxDynamicSharedMemorySize, GSMEM_BYTES);
    cudaFuncSetAttribute(gemm_tc<1>, cudaFuncAttributeMaxDynamicSharedMemorySize, GSMEM_BYTES);

    float *h, *hn, *q, *k, *v, *ao, *s, *t, *cn, *kh, *vh, *qh, *co, *query, *cfn, *cff;
    float *rwq, *rwk, *rwv, *rwo, *rw1, *rw2, *rcqk, *rckk, *rcvk, *rcok, *rcw1, *rcw2;
    cudaGetSymbolAddress((void**)&h,  g_h);
    cudaGetSymbolAddress((void**)&hn, g_hn);
    cudaGetSymbolAddress((void**)&q,  g_q);
    cudaGetSymbolAddress((void**)&k,  g_k);
    cudaGetSymbolAddress((void**)&v,  g_v);
    cudaGetSymbolAddress((void**)&ao, g_ao);
    cudaGetSymbolAddress((void**)&s,  g_s);
    cudaGetSymbolAddress((void**)&t,  g_t);
    cudaGetSymbolAddress((void**)&cn, g_cn);
    cudaGetSymbolAddress((void**)&kh, g_kh);
    cudaGetSymbolAddress((void**)&vh, g_vh);
    cudaGetSymbolAddress((void**)&qh, g_qh);
    cudaGetSymbolAddress((void**)&co, g_co);
    cudaGetSymbolAddress((void**)&query, g_query);
    cudaGetSymbolAddress((void**)&cfn, g_cfn);
    cudaGetSymbolAddress((void**)&cff, g_cff);
    cudaGetSymbolAddress((void**)&rwq, g_rwq);
    cudaGetSymbolAddress((void**)&rwk, g_rwk);
    cudaGetSymbolAddress((void**)&rwv, g_rwv);
    cudaGetSymbolAddress((void**)&rwo, g_rwo);
    cudaGetSymbolAddress((void**)&rw1, g_rw1);
    cudaGetSymbolAddress((void**)&rw2, g_rw2);
    cudaGetSymbolAddress((void**)&rcqk, g_rcqk);
    cudaGetSymbolAddress((void**)&rckk, g_rckk);
    cudaGetSymbolAddress((void**)&rcvk, g_rcvk);
    cudaGetSymbolAddress((void**)&rcok, g_rcok);
    cudaGetSymbolAddress((void**)&rcw1, g_rcw1);
    cudaGetSymbolAddress((void**)&rcw2, g_rcw2);

    detect_mask_kernel<<<1, 1>>>((const unsigned int*)mask);
    copy_kernel<<<(B_*N_*D_ + 255) / 256, 256>>>(x, h, B_*N_*D_);

    // pre-round weights to tf32 (rna) once per launch
    {
        int n1 = L_*D_*D_, n2 = L_*D_*F_, n3 = LC_*D_*D_, n4 = LC_*D_*F_;
        round_kernel<<<(n1 + 255) / 256, 256>>>(p_wq, rwq, n1);
        round_kernel<<<(n1 + 255) / 256, 256>>>(p_wk, rwk, n1);
        round_kernel<<<(n1 + 255) / 256, 256>>>(p_wv, rwv, n1);
        round_kernel<<<(n1 + 255) / 256, 256>>>(p_wo, rwo, n1);
        round_kernel<<<(n2 + 255) / 256, 256>>>(p_w1, rw1, n2);
        round_kernel<<<(n2 + 255) / 256, 256>>>(p_w2, rw2, n2);
        round_kernel<<<(n3 + 255) / 256, 256>>>(c_qk, rcqk, n3);
        round_kernel<<<(n3 + 255) / 256, 256>>>(c_kk, rckk, n3);
        round_kernel<<<(n3 + 255) / 256, 256>>>(c_vk, rcvk, n3);
        round_kernel<<<(n3 + 255) / 256, 256>>>(c_ok, rcok, n3);
        round_kernel<<<(n4 + 255) / 256, 256>>>(c_w1, rcw1, n4);
        round_kernel<<<(n4 + 255) / 256, 256>>>(c_w2, rcw2, n4);
    }

    // -------- particle transformer layers --------
    for (int l = 0; l < L_; l++) {
        const float* wq = rwq + (long)l * D_ * D_;
        const float* wk = rwk + (long)l * D_ * D_;
        const float* wv = rwv + (long)l * D_ * D_;
        const float* wo = rwo + (long)l * D_ * D_;
        const float* w1 = rw1 + (long)l * D_ * F_;
        const float* w2 = rw2 + (long)l * F_ * D_;

        ln_kernel<<<B_*N_, 128>>>(h, hn, p_ln1_g + (long)l * D_, p_ln1_b + (long)l * D_, 1);
        launch_gemm_simple(hn, wq, q, B_*N_, D_, D_, D_, D_, D_, nullptr, nullptr, 0, 0, 1);
        launch_gemm_simple(hn, wk, k, B_*N_, D_, D_, D_, D_, D_, nullptr, nullptr, 0, 0, 1);
        launch_gemm_simple(hn, wv, v, B_*N_, D_, D_, D_, D_, D_, nullptr, nullptr, 0, 0, 1);

        // scores S[b,h,qi,ki] = sum_d Q[b,qi,h,d]*K[b,ki,h,d]
        launch_gemm(q, k, s, N_, N_, DH_, D_, D_, N_,
                    nullptr, nullptr, 0, 0, 0,
                    B_*H_, H_,
                    (long)N_*D_, DH_, (long)N_*D_, DH_, (long)H_*N_*N_, (long)N_*N_,
                    0, 0, true);

        attn_softmax2<<<B_*N_, 256>>>(s, inter, mask);

        // O = A @ V -> ao[b, qi, h*64+dh]
        launch_gemm(s, v, ao, N_, DH_, N_, N_, D_, D_,
                    nullptr, nullptr, 0, 0, 1,
                    B_*H_, H_,
                    (long)H_*N_*N_, (long)N_*N_, (long)N_*D_, DH_, (long)N_*D_, DH_,
                    0, 0, false);

        // h = h + ao @ Wo
        launch_gemm_simple(ao, wo, h, B_*N_, D_, D_, D_, D_, D_, nullptr, h, D_, 0, 0);

        // FFN
        ln_kernel<<<B_*N_, 128>>>(h, hn, p_ln2_g + (long)l * D_, p_ln2_b + (long)l * D_, 1);
        launch_gemm_simple(hn, w1, t, B_*N_, F_, D_, D_, F_, F_,
                           p_b1 + (long)l * F_, nullptr, 0, 1, 1);
        launch_gemm_simple(t, w2, h, B_*N_, D_, F_, F_, D_, D_,
                           p_b2 + (long)l * D_, h, D_, 0, 0);
    }

    // -------- class attention layers --------
    bcast_token_kernel<<<(B_*D_ + 255) / 256, 256>>>(ctok);
    for (int l = 0; l < LC_; l++) {
        ln_cat_kernel<<<B_*NTOK_, 128>>>(query, h, cn,
                                         c_ln1_g + (long)l * D_, c_ln1_b + (long)l * D_);
        launch_gemm_simple(query, rcqk + (long)l * D_ * D_, qh, B_, D_, D_, D_, D_, D_,
                           c_qb + (long)l * D_, nullptr, 0, 0, 0);
        launch_gemm_simple(cn, rckk + (long)l * D_ * D_, kh, B_*NTOK_, D_, D_, D_, D_, D_,
                           c_kb + (long)l * D_, nullptr, 0, 0, 0);
        launch_gemm_simple(cn, rcvk + (long)l * D_ * D_, vh, B_*NTOK_, D_, D_, D_, D_, D_,
                           c_vb + (long)l * D_, nullptr, 0, 0, 0);

        cattn_kernel<<<B_*H_, 128>>>(qh, kh, vh, co, mask);

        launch_gemm_simple(co, rcok + (long)l * D_ * D_, query, B_, D_, D_, D_, D_, D_,
                           c_ob + (long)l * D_, query, D_, 0, 0);

        ln_kernel<<<B_, 128>>>(query, cfn, c_ln2_g + (long)l * D_, c_ln2_b + (long)l * D_, 1);
        launch_gemm_simple(cfn, rcw1 + (long)l * D_ * F_, cff, B_, F_, D_, D_, F_, F_,
                           c_b1 + (long)l * F_, nullptr, 0, 1, 1);
        launch_gemm_simple(cff, rcw2 + (long)l * F_ * D_, query, B_, D_, F_, F_, D_, D_,
                           c_b2 + (long)l * D_, query, D_, 0, 0);
    }

    copy_kernel<<<(B_*D_ + 255) / 256, 256>>>(query, (float*)d_out, B_*D_);
}

// round 5
// speedup vs baseline: 4.8532x; 1.5952x over previous
#include <cuda_runtime.h>
#include <cuda_fp16.h>
#include <math.h>
#include <stdint.h>

#define B_ 32
#define N_ 256
#define D_ 512
#define H_ 8
#define DH_ 64
#define F_ 2048
#define L_ 8
#define LC_ 2
#define NTOK_ 257
#define QKVW_ 1536

// ---------------- scratch (device globals; no allocation allowed) ----------------
static __device__ float  g_h  [B_*N_*D_];
static __device__ __half g_hn [B_*N_*D_];
static __device__ __half g_qkv[B_*N_*QKVW_];
static __device__ __half g_ao [B_*N_*D_];
static __device__ float  g_s  [B_*H_*N_*N_];
static __device__ __half g_sh [B_*H_*N_*N_];
static __device__ __half g_t  [B_*N_*F_];
static __device__ __half g_cn [B_*NTOK_*D_];
static __device__ float  g_kh [B_*NTOK_*D_];
static __device__ float  g_vh [B_*NTOK_*D_];
static __device__ float  g_qh [B_*D_];
static __device__ __half g_co [B_*D_];
static __device__ float  g_query[B_*D_];
static __device__ __half g_queryh[B_*D_];
static __device__ __half g_cfn[B_*D_];
static __device__ __half g_cff[B_*F_];
static __device__ int    g_mask_mode;

// transposed fp16 weights: [N][K] row-major
static __device__ __half g_wqkvT[L_*QKVW_*D_];
static __device__ __half g_woT [L_*D_*D_];
static __device__ __half g_w1T [L_*F_*D_];
static __device__ __half g_w2T [L_*D_*F_];
static __device__ __half g_cqkT[LC_*D_*D_];
static __device__ __half g_ckkT[LC_*D_*D_];
static __device__ __half g_cvkT[LC_*D_*D_];
static __device__ __half g_cokT[LC_*D_*D_];
static __device__ __half g_cw1T[LC_*F_*D_];
static __device__ __half g_cw2T[LC_*D_*F_];

// ---------------- mask dtype detection ----------------
__global__ void detect_mask_kernel(const unsigned int* m) {
    unsigned int w = m[0];
    int mode = 0;
    if (w == 0x01010101u) mode = 1;
    else if (w == 0x3F800000u) mode = 2;
    g_mask_mode = mode;
}

__device__ __forceinline__ bool mget(const void* m, int idx) {
    int mode = g_mask_mode;
    if (mode == 1) return ((const unsigned char*)m)[idx] != 0;
    if (mode == 2) return ((const float*)m)[idx] != 0.0f;
    return ((const int*)m)[idx] != 0;
}

// ---------------- tiny utility kernels ----------------
__global__ void copy_kernel(const float* __restrict__ src, float* __restrict__ dst, int n) {
    int i = blockIdx.x * 256 + threadIdx.x;
    if (i < n) dst[i] = src[i];
}

__global__ void f2h_kernel(const float* __restrict__ src, __half* __restrict__ dst, int n) {
    int i = blockIdx.x * 256 + threadIdx.x;
    if (i < n) dst[i] = __float2half(src[i]);
}

__global__ void bcast_token_kernel(const float* __restrict__ tok) {
    int i = blockIdx.x * 256 + threadIdx.x;
    if (i < B_*D_) g_query[i] = tok[i % D_];
}

// src [K,N] f32 row-major -> dst [N,K] half row-major; batched over z.
__global__ void transpose_h(const float* __restrict__ src, __half* __restrict__ dst,
                            int K, int N, long sStride, long dStride) {
    __shared__ float tile[32][33];
    src += (long)blockIdx.z * sStride;
    dst += (long)blockIdx.z * dStride;
    int k0 = blockIdx.y * 32, n0 = blockIdx.x * 32;
    int tx = threadIdx.x, ty = threadIdx.y; // 32 x 8
    #pragma unroll
    for (int i = 0; i < 32; i += 8)
        tile[ty + i][tx] = src[(long)(k0 + ty + i) * N + n0 + tx];
    __syncthreads();
    #pragma unroll
    for (int i = 0; i < 32; i += 8)
        dst[(long)(n0 + ty + i) * K + k0 + tx] = __float2half(tile[tx][ty + i]);
}

// ---------------- LayerNorm (eps = 1e-3), half output ----------------
__device__ __forceinline__ void ln_row(const float* __restrict__ x, __half* __restrict__ o,
                                       const float* __restrict__ g, const float* __restrict__ bb) {
    int tid = threadIdx.x; // 128 threads
    float s = 0.f, s2 = 0.f;
    #pragma unroll
    for (int i = tid; i < D_; i += 128) { float v = x[i]; s += v; s2 += v * v; }
    __shared__ float sh[8];
    #pragma unroll
    for (int off = 16; off; off >>= 1) {
        s  += __shfl_xor_sync(0xffffffffu, s,  off);
        s2 += __shfl_xor_sync(0xffffffffu, s2, off);
    }
    if ((tid & 31) == 0) { sh[tid >> 5] = s; sh[4 + (tid >> 5)] = s2; }
    __syncthreads();
    s  = sh[0] + sh[1] + sh[2] + sh[3];
    s2 = sh[4] + sh[5] + sh[6] + sh[7];
    float mean = s * (1.f / D_);
    float var  = s2 * (1.f / D_) - mean * mean;
    float r = rsqrtf(var + 1e-3f);
    #pragma unroll
    for (int i = tid; i < D_; i += 128)
        o[i] = __float2half((x[i] - mean) * r * g[i] + bb[i]);
}

__global__ void ln_kernel(const float* __restrict__ in, __half* __restrict__ out,
                          const float* __restrict__ g, const float* __restrict__ b) {
    long row = blockIdx.x;
    ln_row(in + row * D_, out + row * D_, g, b);
}

__global__ void ln_cat_kernel(const float* __restrict__ query, const float* __restrict__ h,
                              __half* __restrict__ out,
                              const float* __restrict__ g, const float* __restrict__ b) {
    int row = blockIdx.x;
    int bb = row / NTOK_, sidx = row % NTOK_;
    const float* x = (sidx == 0) ? (query + (long)bb * D_)
                                 : (h + ((long)(bb * N_) + sidx - 1) * D_);
    ln_row(x, out + (long)row * D_, g, b);
}

// ---------------- cp.async helpers ----------------
__device__ __forceinline__ void cp16(void* smem_ptr, const void* gptr, bool pred) {
    uint32_t sa = (uint32_t)__cvta_generic_to_shared(smem_ptr);
    int sz = pred ? 16 : 0;
    asm volatile("cp.async.cg.shared.global [%0], [%1], 16, %2;\n" :: "r"(sa), "l"(gptr), "r"(sz));
}
__device__ __forceinline__ void cp_commit() {
    asm volatile("cp.async.commit_group;\n" ::: "memory");
}
template<int NN>
__device__ __forceinline__ void cp_wait() {
    asm volatile("cp.async.wait_group %0;\n" :: "n"(NN) : "memory");
}

// ---------------- fp16 tensor-core GEMM ----------------
__device__ __forceinline__ void mma_f16(float c[4], const unsigned a[4], const unsigned b[2]) {
    asm volatile(
        "mma.sync.aligned.m16n8k16.row.col.f32.f16.f16.f32 "
        "{%0,%1,%2,%3}, {%4,%5,%6,%7}, {%8,%9}, {%0,%1,%2,%3};\n"
        : "+f"(c[0]), "+f"(c[1]), "+f"(c[2]), "+f"(c[3])
        : "r"(a[0]), "r"(a[1]), "r"(a[2]), "r"(a[3]), "r"(b[0]), "r"(b[1]));
}

// BM=128, BN=128, BK=32, 256 threads (8 warps = 2Mx4N, warp tile 64x32), 3 stages.
// A smem [m][k] stride 40 halves (bank-conflict-free); B TRANSB [n][k] stride 40;
// B notrans [k][n] stride 136 halves.
#define HSTAGES 3
#define STAGE_H 5120
#define HSMEM_BYTES (2 * HSTAGES * STAGE_H * 2)   // 61440

template<int TRANSB>
__global__ void __launch_bounds__(256, 2) gemm_h(
    const __half* __restrict__ A, const __half* __restrict__ Bm, void* __restrict__ Cv,
    int M, int Nn, int K, int lda, int ldb, int ldc,
    int zdiv, long sA1, long sA2, long sB1, long sB2, long sC1, long sC2,
    const float* __restrict__ bias, const float* __restrict__ res, int ldr,
    long sR1, long sR2, int act, int cmode)
{
    extern __shared__ __half dynh[];

    int z = blockIdx.z;
    long z1 = z / zdiv, z2 = z % zdiv;
    A  += z1 * sA1 + z2 * sA2;
    Bm += z1 * sB1 + z2 * sB2;
    long coff = z1 * sC1 + z2 * sC2;
    if (res) res += z1 * sR1 + z2 * sR2;

    const int tid  = threadIdx.x;
    const int wid  = tid >> 5, lane = tid & 31;
    const int wM   = wid >> 2, wN = wid & 3;
    const int g    = lane >> 2, tg = lane & 3;
    const int m0   = blockIdx.y * 128, n0 = blockIdx.x * 128;

    float acc[4][4][4];
    #pragma unroll
    for (int i = 0; i < 4; i++)
        #pragma unroll
        for (int j = 0; j < 4; j++)
            #pragma unroll
            for (int r = 0; r < 4; r++) acc[i][j][r] = 0.f;

    auto load_stage = [&](int buf, int k0) {
        #pragma unroll
        for (int i = 0; i < 2; i++) {            // A: 128 x 32 halves
            int c = tid + i * 256;
            int row = c >> 2, col = (c & 3) << 3;
            bool p = (m0 + row) < M;
            const __half* gp = p ? (A + (long)(m0 + row) * lda + k0 + col) : A;
            cp16(dynh + buf * STAGE_H + row * 40 + col, gp, p);
        }
        if (TRANSB) {
            #pragma unroll
            for (int i = 0; i < 2; i++) {        // B: 128 x 32 halves
                int c = tid + i * 256;
                int row = c >> 2, col = (c & 3) << 3;
                bool p = (n0 + row) < Nn;
                const __half* gp = p ? (Bm + (long)(n0 + row) * ldb + k0 + col) : Bm;
                cp16(dynh + (HSTAGES + buf) * STAGE_H + row * 40 + col, gp, p);
            }
        } else {
            #pragma unroll
            for (int i = 0; i < 2; i++) {        // B: 32 x 128 halves
                int c = tid + i * 256;
                int row = c >> 4, col = (c & 15) << 3;
                bool p = (n0 + col) < Nn;
                const __half* gp = p ? (Bm + (long)(k0 + row) * ldb + n0 + col) : Bm;
                cp16(dynh + (HSTAGES + buf) * STAGE_H + row * 136 + col, gp, p);
            }
        }
    };

    auto compute = [&](int buf) {
        const __half* As = dynh + buf * STAGE_H;
        const __half* Bs = dynh + (HSTAGES + buf) * STAGE_H;
        #pragma unroll
        for (int ks = 0; ks < 32; ks += 16) {
            unsigned af[4][4], bf[4][2];
            #pragma unroll
            for (int mt = 0; mt < 4; mt++) {
                int m = wM * 64 + mt * 16 + g;
                af[mt][0] = *(const unsigned*)(As + (m    ) * 40 + ks + 2 * tg);
                af[mt][1] = *(const unsigned*)(As + (m + 8) * 40 + ks + 2 * tg);
                af[mt][2] = *(const unsigned*)(As + (m    ) * 40 + ks + 2 * tg + 8);
                af[mt][3] = *(const unsigned*)(As + (m + 8) * 40 + ks + 2 * tg + 8);
            }
            #pragma unroll
            for (int nt = 0; nt < 4; nt++) {
                int n = wN * 32 + nt * 8 + g;
                if (TRANSB) {
                    bf[nt][0] = *(const unsigned*)(Bs + n * 40 + ks + 2 * tg);
                    bf[nt][1] = *(const unsigned*)(Bs + n * 40 + ks + 2 * tg + 8);
                } else {
                    unsigned l0 = *(const unsigned short*)(Bs + (ks + 2 * tg    ) * 136 + n);
                    unsigned h0 = *(const unsigned short*)(Bs + (ks + 2 * tg + 1) * 136 + n);
                    unsigned l1 = *(const unsigned short*)(Bs + (ks + 2 * tg + 8) * 136 + n);
                    unsigned h1 = *(const unsigned short*)(Bs + (ks + 2 * tg + 9) * 136 + n);
                    bf[nt][0] = l0 | (h0 << 16);
                    bf[nt][1] = l1 | (h1 << 16);
                }
            }
            #pragma unroll
            for (int mt = 0; mt < 4; mt++)
                #pragma unroll
                for (int nt = 0; nt < 4; nt++)
                    mma_f16(acc[mt][nt], af[mt], bf[nt]);
        }
    };

    const int KT = K >> 5;
    #pragma unroll
    for (int s = 0; s < HSTAGES - 1; s++) {
        if (s < KT) load_stage(s, s * 32);
        cp_commit();
    }
    for (int kt = 0; kt < KT; kt++) {
        cp_wait<HSTAGES - 2>();
        __syncthreads();
        int pf = kt + HSTAGES - 1;
        if (pf < KT) load_stage(pf % HSTAGES, pf * 32);
        cp_commit();
        compute(kt % HSTAGES);
    }
    cp_wait<0>();

    // ---- epilogue ----
    #pragma unroll
    for (int mt = 0; mt < 4; mt++) {
        #pragma unroll
        for (int nt = 0; nt < 4; nt++) {
            int m = m0 + wM * 64 + mt * 16 + g;
            int n = n0 + wN * 32 + nt * 8 + tg * 2;
            if (n >= Nn) continue;
            float bx = 0.f, by = 0.f;
            if (bias) { bx = bias[n]; by = bias[n + 1]; }
            #pragma unroll
            for (int half = 0; half < 2; half++) {
                int mm = m + half * 8;
                if (mm >= M) continue;
                float2 v = make_float2(acc[mt][nt][half * 2], acc[mt][nt][half * 2 + 1]);
                if (bias) { v.x += bx; v.y += by; }
                if (act) {
                    v.x = 0.5f * v.x * (1.f + erff(v.x * 0.70710678118654752f));
                    v.y = 0.5f * v.y * (1.f + erff(v.y * 0.70710678118654752f));
                }
                if (res) {
                    float2 r = *(const float2*)(res + (long)mm * ldr + n);
                    v.x += r.x; v.y += r.y;
                }
                if (cmode) {
                    __half2 hv = __floats2half2_rn(v.x, v.y);
                    *(__half2*)((__half*)Cv + coff + (long)mm * ldc + n) = hv;
                } else {
                    *(float2*)((float*)Cv + coff + (long)mm * ldc + n) = v;
                }
            }
        }
    }
}

// ---------------- masked softmax with interaction bias ----------------
__global__ void attn_softmax2(const float* __restrict__ s, __half* __restrict__ sh,
                              const float* __restrict__ inter, const void* __restrict__ mask) {
    int row = blockIdx.x;           // b*N + qi
    int qi = row % N_, b = row / N_;
    int k = threadIdx.x;            // 256 threads
    int lane = k & 31, w = k >> 5;
    bool qm = mget(mask, b * N_ + qi);
    bool km = mget(mask, b * N_ + k);
    float madd = (qm && km) ? 0.f : -1e9f;
    const float4* ip = (const float4*)(inter + ((long)row * N_ + k) * H_);
    float4 i0 = ip[0], i1 = ip[1];
    float iv[8] = {i0.x, i0.y, i0.z, i0.w, i1.x, i1.y, i1.z, i1.w};
    __shared__ float red[8];
    #pragma unroll
    for (int h = 0; h < H_; h++) {
        long off = (((long)b * H_ + h) * N_ + qi) * N_;
        float v = s[off + k] * 0.125f + iv[h] + madd;
        float m = v;
        #pragma unroll
        for (int o = 16; o; o >>= 1) m = fmaxf(m, __shfl_xor_sync(0xffffffffu, m, o));
        if (lane == 0) red[w] = m;
        __syncthreads();
        m = fmaxf(fmaxf(fmaxf(red[0], red[1]), fmaxf(red[2], red[3])),
                  fmaxf(fmaxf(red[4], red[5]), fmaxf(red[6], red[7])));
        float e = expf(v - m);
        float sm = e;
        #pragma unroll
        for (int o = 16; o; o >>= 1) sm += __shfl_xor_sync(0xffffffffu, sm, o);
        __syncthreads();
        if (lane == 0) red[w] = sm;
        __syncthreads();
        sm = red[0] + red[1] + red[2] + red[3] + red[4] + red[5] + red[6] + red[7];
        sh[off + k] = __float2half(e / sm);
        __syncthreads();
    }
}

// ---------------- class attention core (per b,h) ----------------
__global__ void cattn_kernel(const float* __restrict__ qh, const float* __restrict__ kh,
                             const float* __restrict__ vh, __half* __restrict__ co,
                             const void* __restrict__ mask) {
    int z = blockIdx.x;
    int b = z / H_, h = z % H_;
    int tid = threadIdx.x; // 128 threads
    __shared__ float a[NTOK_];
    __shared__ float red[4];
    const float* qv = qh + (long)b * D_ + h * DH_;
    float lmax = -3.0e38f;
    for (int sidx = tid; sidx < NTOK_; sidx += 128) {
        const float* kv = kh + ((long)(b * NTOK_ + sidx)) * D_ + h * DH_;
        float sc = 0.f;
        #pragma unroll
        for (int d = 0; d < DH_; d++) sc += qv[d] * kv[d];
        sc = sc * 0.125f + ((sidx == 0 || mget(mask, b * N_ + sidx - 1)) ? 0.f : -1e9f);
        a[sidx] = sc;
        lmax = fmaxf(lmax, sc);
    }
    #pragma unroll
    for (int off = 16; off; off >>= 1) lmax = fmaxf(lmax, __shfl_xor_sync(0xffffffffu, lmax, off));
    if ((tid & 31) == 0) red[tid >> 5] = lmax;
    __syncthreads();
    float m = fmaxf(fmaxf(red[0], red[1]), fmaxf(red[2], red[3]));
    __syncthreads();
    float lsum = 0.f;
    for (int sidx = tid; sidx < NTOK_; sidx += 128) {
        float e = expf(a[sidx] - m);
        a[sidx] = e;
        lsum += e;
    }
    #pragma unroll
    for (int off = 16; off; off >>= 1) lsum += __shfl_xor_sync(0xffffffffu, lsum, off);
    if ((tid & 31) == 0) red[tid >> 5] = lsum;
    __syncthreads();
    float inv = 1.f / (red[0] + red[1] + red[2] + red[3]);
    if (tid < DH_) {
        float o = 0.f;
        for (int sidx = 0; sidx < NTOK_; sidx++)
            o += a[sidx] * vh[((long)(b * NTOK_ + sidx)) * D_ + h * DH_ + tid];
        co[(long)b * D_ + h * DH_ + tid] = __float2half(o * inv);
    }
}

// ---------------- host-side launch helpers ----------------
static void launch_gemm(const __half* A, const __half* Bm, void* C,
                        int M, int Nn, int K, int lda, int ldb, int ldc,
                        const float* bias, const float* res, int ldr, int act, int cmode,
                        int nz, int zdiv,
                        long sA1, long sA2, long sB1, long sB2, long sC1, long sC2,
                        long sR1, long sR2, bool transb) {
    dim3 grid((Nn + 127) / 128, (M + 127) / 128, nz);
    if (transb)
        gemm_h<1><<<grid, 256, HSMEM_BYTES>>>(A, Bm, C, M, Nn, K, lda, ldb, ldc,
                                              zdiv, sA1, sA2, sB1, sB2, sC1, sC2,
                                              bias, res, ldr, sR1, sR2, act, cmode);
    else
        gemm_h<0><<<grid, 256, HSMEM_BYTES>>>(A, Bm, C, M, Nn, K, lda, ldb, ldc,
                                              zdiv, sA1, sA2, sB1, sB2, sC1, sC2,
                                              bias, res, ldr, sR1, sR2, act, cmode);
}

static void launch_gemm_simple(const __half* A, const __half* Bm, void* C,
                               int M, int Nn, int K, int lda, int ldb, int ldc,
                               const float* bias, const float* res, int ldr,
                               int act, int cmode) {
    launch_gemm(A, Bm, C, M, Nn, K, lda, ldb, ldc, bias, res, ldr, act, cmode,
                1, 1, 0, 0, 0, 0, 0, 0, 0, 0, true);
}

extern "C" void kernel_launch(void* const* d_in, const int* in_sizes, int n_in,
                              void* d_out, int out_size) {
    const float* x       = (const float*)d_in[0];
    const float* inter   = (const float*)d_in[1];
    const float* ctok    = (const float*)d_in[2];
    const float* p_ln1_g = (const float*)d_in[3];
    const float* p_ln1_b = (const float*)d_in[4];
    const float* p_wq    = (const float*)d_in[5];
    const float* p_wk    = (const float*)d_in[6];
    const float* p_wv    = (const float*)d_in[7];
    const float* p_wo    = (const float*)d_in[8];
    const float* p_ln2_g = (const float*)d_in[9];
    const float* p_ln2_b = (const float*)d_in[10];
    const float* p_w1    = (const float*)d_in[11];
    const float* p_b1    = (const float*)d_in[12];
    const float* p_w2    = (const float*)d_in[13];
    const float* p_b2    = (const float*)d_in[14];
    const float* c_ln1_g = (const float*)d_in[15];
    const float* c_ln1_b = (const float*)d_in[16];
    const float* c_qk    = (const float*)d_in[17];
    const float* c_qb    = (const float*)d_in[18];
    const float* c_kk    = (const float*)d_in[19];
    const float* c_kb    = (const float*)d_in[20];
    const float* c_vk    = (const float*)d_in[21];
    const float* c_vb    = (const float*)d_in[22];
    const float* c_ok    = (const float*)d_in[23];
    const float* c_ob    = (const float*)d_in[24];
    const float* c_ln2_g = (const float*)d_in[25];
    const float* c_ln2_b = (const float*)d_in[26];
    const float* c_w1    = (const float*)d_in[27];
    const float* c_b1    = (const float*)d_in[28];
    const float* c_w2    = (const float*)d_in[29];
    const float* c_b2    = (const float*)d_in[30];
    const void*  mask    = d_in[31];

    cudaFuncSetAttribute(gemm_h<0>, cudaFuncAttributeMaxDynamicSharedMemorySize, HSMEM_BYTES);
    cudaFuncSetAttribute(gemm_h<1>, cudaFuncAttributeMaxDynamicSharedMemorySize, HSMEM_BYTES);

    float *h, *s, *kh, *vh, *qh, *query;
    __half *hn, *qkv, *ao, *shp, *t, *cn, *co, *queryh, *cfn, *cff;
    __half *wqkvT, *woT, *w1T, *w2T, *cqkT, *ckkT, *cvkT, *cokT, *cw1T, *cw2T;
    cudaGetSymbolAddress((void**)&h,     g_h);
    cudaGetSymbolAddress((void**)&hn,    g_hn);
    cudaGetSymbolAddress((void**)&qkv,   g_qkv);
    cudaGetSymbolAddress((void**)&ao,    g_ao);
    cudaGetSymbolAddress((void**)&s,     g_s);
    cudaGetSymbolAddress((void**)&shp,   g_sh);
    cudaGetSymbolAddress((void**)&t,     g_t);
    cudaGetSymbolAddress((void**)&cn,    g_cn);
    cudaGetSymbolAddress((void**)&kh,    g_kh);
    cudaGetSymbolAddress((void**)&vh,    g_vh);
    cudaGetSymbolAddress((void**)&qh,    g_qh);
    cudaGetSymbolAddress((void**)&co,    g_co);
    cudaGetSymbolAddress((void**)&query, g_query);
    cudaGetSymbolAddress((void**)&queryh,g_queryh);
    cudaGetSymbolAddress((void**)&cfn,   g_cfn);
    cudaGetSymbolAddress((void**)&cff,   g_cff);
    cudaGetSymbolAddress((void**)&wqkvT, g_wqkvT);
    cudaGetSymbolAddress((void**)&woT,   g_woT);
    cudaGetSymbolAddress((void**)&w1T,   g_w1T);
    cudaGetSymbolAddress((void**)&w2T,   g_w2T);
    cudaGetSymbolAddress((void**)&cqkT,  g_cqkT);
    cudaGetSymbolAddress((void**)&ckkT,  g_ckkT);
    cudaGetSymbolAddress((void**)&cvkT,  g_cvkT);
    cudaGetSymbolAddress((void**)&cokT,  g_cokT);
    cudaGetSymbolAddress((void**)&cw1T,  g_cw1T);
    cudaGetSymbolAddress((void**)&cw2T,  g_cw2T);

    detect_mask_kernel<<<1, 1>>>((const unsigned int*)mask);
    copy_kernel<<<(B_*N_*D_ + 255) / 256, 256>>>(x, h, B_*N_*D_);

    // weight prep: transpose + fp16 (batched over layers)
    {
        dim3 blk(32, 8);
        dim3 gDD(D_/32, D_/32, L_);
        transpose_h<<<gDD, blk>>>(p_wq, wqkvT + 0L*D_,    D_, D_, (long)D_*D_, (long)QKVW_*D_);
        transpose_h<<<gDD, blk>>>(p_wk, wqkvT + 512L*D_,  D_, D_, (long)D_*D_, (long)QKVW_*D_);
        transpose_h<<<gDD, blk>>>(p_wv, wqkvT + 1024L*D_, D_, D_, (long)D_*D_, (long)QKVW_*D_);
        transpose_h<<<gDD, blk>>>(p_wo, woT,              D_, D_, (long)D_*D_, (long)D_*D_);
        dim3 gDF(F_/32, D_/32, L_);
        transpose_h<<<gDF, blk>>>(p_w1, w1T, D_, F_, (long)D_*F_, (long)F_*D_);
        dim3 gFD(D_/32, F_/32, L_);
        transpose_h<<<gFD, blk>>>(p_w2, w2T, F_, D_, (long)F_*D_, (long)D_*F_);
        dim3 cDD(D_/32, D_/32, LC_);
        transpose_h<<<cDD, blk>>>(c_qk, cqkT, D_, D_, (long)D_*D_, (long)D_*D_);
        transpose_h<<<cDD, blk>>>(c_kk, ckkT, D_, D_, (long)D_*D_, (long)D_*D_);
        transpose_h<<<cDD, blk>>>(c_vk, cvkT, D_, D_, (long)D_*D_, (long)D_*D_);
        transpose_h<<<cDD, blk>>>(c_ok, cokT, D_, D_, (long)D_*D_, (long)D_*D_);
        dim3 cDF(F_/32, D_/32, LC_);
        transpose_h<<<cDF, blk>>>(c_w1, cw1T, D_, F_, (long)D_*F_, (long)F_*D_);
        dim3 cFD(D_/32, F_/32, LC_);
        transpose_h<<<cFD, blk>>>(c_w2, cw2T, F_, D_, (long)F_*D_, (long)D_*F_);
    }

    // -------- particle transformer layers --------
    for (int l = 0; l < L_; l++) {
        ln_kernel<<<B_*N_, 128>>>(h, hn, p_ln1_g + (long)l * D_, p_ln1_b + (long)l * D_);

        // fused QKV -> qkv[M, 1536] (half)
        launch_gemm_simple(hn, wqkvT + (long)l * QKVW_ * D_, qkv,
                           B_*N_, QKVW_, D_, D_, D_, QKVW_, nullptr, nullptr, 0, 0, 1);

        // scores S[b,h,qi,ki] (fp32): Q cols 0-511, K cols 512-1023, lda=1536
        launch_gemm(qkv, qkv + 512, s, N_, N_, DH_, QKVW_, QKVW_, N_,
                    nullptr, nullptr, 0, 0, 0,
                    B_*H_, H_,
                    (long)N_*QKVW_, DH_, (long)N_*QKVW_, DH_, (long)H_*N_*N_, (long)N_*N_,
                    0, 0, true);

        attn_softmax2<<<B_*N_, 256>>>(s, shp, inter, mask);

        // O = P @ V (V cols 1024-1535, notrans) -> ao (half)
        launch_gemm(shp, qkv + 1024, ao, N_, DH_, N_, N_, QKVW_, D_,
                    nullptr, nullptr, 0, 0, 1,
                    B_*H_, H_,
                    (long)H_*N_*N_, (long)N_*N_, (long)N_*QKVW_, DH_, (long)N_*D_, DH_,
                    0, 0, false);

        // h = h + ao @ Wo
        launch_gemm_simple(ao, woT + (long)l * D_ * D_, h,
                           B_*N_, D_, D_, D_, D_, D_, nullptr, h, D_, 0, 0);

        // FFN
        ln_kernel<<<B_*N_, 128>>>(h, hn, p_ln2_g + (long)l * D_, p_ln2_b + (long)l * D_);
        launch_gemm_simple(hn, w1T + (long)l * F_ * D_, t,
                           B_*N_, F_, D_, D_, D_, F_, p_b1 + (long)l * F_, nullptr, 0, 1, 1);
        launch_gemm_simple(t, w2T + (long)l * D_ * F_, h,
                           B_*N_, D_, F_, F_, F_, D_, p_b2 + (long)l * D_, h, D_, 0, 0);
    }

    // -------- class attention layers --------
    bcast_token_kernel<<<(B_*D_ + 255) / 256, 256>>>(ctok);
    for (int l = 0; l < LC_; l++) {
        ln_cat_kernel<<<B_*NTOK_, 128>>>(query, h, cn,
                                         c_ln1_g + (long)l * D_, c_ln1_b + (long)l * D_);
        f2h_kernel<<<(B_*D_ + 255) / 256, 256>>>(query, queryh, B_*D_);
        launch_gemm_simple(queryh, cqkT + (long)l * D_ * D_, qh, B_, D_, D_, D_, D_, D_,
                           c_qb + (long)l * D_, nullptr, 0, 0, 0);
        launch_gemm_simple(cn, ckkT + (long)l * D_ * D_, kh, B_*NTOK_, D_, D_, D_, D_, D_,
                           c_kb + (long)l * D_, nullptr, 0, 0, 0);
        launch_gemm_simple(cn, cvkT + (long)l * D_ * D_, vh, B_*NTOK_, D_, D_, D_, D_, D_,
                           c_vb + (long)l * D_, nullptr, 0, 0, 0);

        cattn_kernel<<<B_*H_, 128>>>(qh, kh, vh, co, mask);

        launch_gemm_simple(co, cokT + (long)l * D_ * D_, query, B_, D_, D_, D_, D_, D_,
                           c_ob + (long)l * D_, query, D_, 0, 0);

        ln_kernel<<<B_, 128>>>(query, cfn, c_ln2_g + (long)l * D_, c_ln2_b + (long)l * D_);
        launch_gemm_simple(cfn, cw1T + (long)l * F_ * D_, cff, B_, F_, D_, D_, D_, F_,
                           c_b1 + (long)l * F_, nullptr, 0, 1, 1);
        launch_gemm_simple(cff, cw2T + (long)l * D_ * F_, query, B_, D_, F_, F_, F_, D_,
                           c_b2 + (long)l * D_, query, D_, 0, 0);
    }

    copy_kernel<<<(B_*D_ + 255) / 256, 256>>>(query, (float*)d_out, B_*D_);
}